// round 1
// baseline (speedup 1.0000x reference)
#include <cuda_runtime.h>
#include <cstdint>

#define BV 8
#define NV 2048
#define EV 256
#define HV 512
#define MROWS (BV*NV)   // 16384

// ---- scratch (static device globals; no runtime allocation) ----
__device__ float g_h[(size_t)MROWS * HV];       // 32 MB  relu(emb@W1^T+b1)
__device__ float g_hidden[(size_t)MROWS * HV];  // 32 MB  h@W2^T+b2
__device__ float g_norm[(size_t)MROWS * HV];    // 32 MB  row-normalized hidden
__device__ float g_c[BV * NV];                  // column sums of softplus(sim)
__device__ float g_wit[BV * HV];                // witness

constexpr int BM = 128, BN = 128, BK = 16;

// ============================================================
// MODE 0: out = relu(gather(emb,tokens) @ W1^T + b1) -> g_h     (K=256)
// MODE 1: out = g_h @ W2^T + b2                      -> g_hidden (K=512)
// 256 threads, 128x128 tile, 8x8 microtile (split-half layout).
// ============================================================
template<int MODE>
__global__ __launch_bounds__(256)
void gemm_kernel(const float* __restrict__ Aext, const int* __restrict__ tokens,
                 const float* __restrict__ W, const float* __restrict__ bias)
{
    constexpr int KD = (MODE == 0) ? EV : HV;
    __shared__ float As[BK][BM];
    __shared__ float Bs[BK][BN];
    __shared__ const float* rowPtr[BM];

    const int tid = threadIdx.x;
    const int rowBase = blockIdx.x * BM;
    const int colBase = blockIdx.y * BN;

    if (tid < BM) {
        int r = rowBase + tid;
        if (MODE == 0) rowPtr[tid] = Aext + (size_t)tokens[r] * EV;
        else           rowPtr[tid] = g_h + (size_t)r * HV;
    }
    __syncthreads();

    const int tx = tid & 15, ty = tid >> 4;
    float acc[8][8];
#pragma unroll
    for (int i = 0; i < 8; i++)
#pragma unroll
        for (int j = 0; j < 8; j++) acc[i][j] = 0.f;

    for (int k0 = 0; k0 < KD; k0 += BK) {
        // A tile: 128 rows x 16 k = 512 float4 slots, 2 per thread
#pragma unroll
        for (int l = 0; l < 2; l++) {
            int s = tid + l * 256;
            int r = s >> 2;
            int kq = s & 3;
            float4 v = *(const float4*)(rowPtr[r] + k0 + kq * 4);
            As[kq * 4 + 0][r] = v.x; As[kq * 4 + 1][r] = v.y;
            As[kq * 4 + 2][r] = v.z; As[kq * 4 + 3][r] = v.w;
        }
        // B tile: W rows colBase..colBase+127
#pragma unroll
        for (int l = 0; l < 2; l++) {
            int s = tid + l * 256;
            int r = s >> 2;
            int kq = s & 3;
            float4 v = *(const float4*)(W + (size_t)(colBase + r) * KD + k0 + kq * 4);
            Bs[kq * 4 + 0][r] = v.x; Bs[kq * 4 + 1][r] = v.y;
            Bs[kq * 4 + 2][r] = v.z; Bs[kq * 4 + 3][r] = v.w;
        }
        __syncthreads();
#pragma unroll
        for (int kk = 0; kk < BK; kk++) {
            float a[8], b[8];
            *(float4*)&a[0] = *(const float4*)&As[kk][ty * 4];
            *(float4*)&a[4] = *(const float4*)&As[kk][64 + ty * 4];
            *(float4*)&b[0] = *(const float4*)&Bs[kk][tx * 4];
            *(float4*)&b[4] = *(const float4*)&Bs[kk][64 + tx * 4];
#pragma unroll
            for (int i = 0; i < 8; i++)
#pragma unroll
                for (int j = 0; j < 8; j++)
                    acc[i][j] = fmaf(a[i], b[j], acc[i][j]);
        }
        __syncthreads();
    }

    float* outp = (MODE == 0) ? g_h : g_hidden;
#pragma unroll
    for (int i = 0; i < 8; i++) {
        int rl = (i < 4) ? (ty * 4 + i) : (64 + ty * 4 + i - 4);
        size_t rowOff = (size_t)(rowBase + rl) * HV;
#pragma unroll
        for (int jh = 0; jh < 2; jh++) {
            int c = colBase + (jh ? (64 + tx * 4) : (tx * 4));
            float4 o;
            o.x = acc[i][jh * 4 + 0] + bias[c + 0];
            o.y = acc[i][jh * 4 + 1] + bias[c + 1];
            o.z = acc[i][jh * 4 + 2] + bias[c + 2];
            o.w = acc[i][jh * 4 + 3] + bias[c + 3];
            if (MODE == 0) {
                o.x = fmaxf(o.x, 0.f); o.y = fmaxf(o.y, 0.f);
                o.z = fmaxf(o.z, 0.f); o.w = fmaxf(o.w, 0.f);
            }
            *(float4*)(outp + rowOff + c) = o;
        }
    }
}

// ============================================================
// Row-normalize: g_norm[r] = g_hidden[r] / max(||g_hidden[r]||, 1e-12)
// One block (128 threads) per row; each thread handles one float4.
// ============================================================
__global__ __launch_bounds__(128)
void norm_kernel()
{
    const int row = blockIdx.x;
    const int t = threadIdx.x;
    const float4 x = ((const float4*)(g_hidden + (size_t)row * HV))[t];
    float ss = x.x * x.x + x.y * x.y + x.z * x.z + x.w * x.w;
#pragma unroll
    for (int o = 16; o; o >>= 1) ss += __shfl_xor_sync(0xffffffffu, ss, o);
    __shared__ float wsum[4];
    if ((t & 31) == 0) wsum[t >> 5] = ss;
    __syncthreads();
    float tot = wsum[0] + wsum[1] + wsum[2] + wsum[3];
    float inv = 1.0f / fmaxf(sqrtf(tot), 1e-12f);
    float4 o4 = make_float4(x.x * inv, x.y * inv, x.z * inv, x.w * inv);
    ((float4*)(g_norm + (size_t)row * HV))[t] = o4;
}

__global__ void zero_c_kernel()
{
    int i = blockIdx.x * blockDim.x + threadIdx.x;
    if (i < BV * NV) g_c[i] = 0.f;
}

// ============================================================
// Triangular sim tiles: for batch b, tile (ti<=tj) of 128x128,
// sim = norm[nTile] @ norm[mTile]^T, softplus, then
//   c[m] += column sums (over n); if ti!=tj also c[n] += row sums (over m).
// Grid: (136, B). Same 8x8 microtile SGEMM core, K=512.
// ============================================================
__global__ __launch_bounds__(256)
void sim_kernel()
{
    const int b = blockIdx.y;
    // decode linear upper-triangular tile index -> (ti, tj), ti<=tj, 16x16 tiles
    int rem = blockIdx.x, ti = 0;
    while (rem >= (16 - ti)) { rem -= (16 - ti); ti++; }
    const int tj = ti + rem;
    const int nBase = ti * BM;
    const int mBase = tj * BN;
    const float* base = g_norm + (size_t)b * NV * HV;

    __shared__ float As[BK][BM];
    __shared__ float Bs[BK][BN];
    __shared__ float red[16][128];

    const int tid = threadIdx.x;
    const int tx = tid & 15, ty = tid >> 4;

    float acc[8][8];
#pragma unroll
    for (int i = 0; i < 8; i++)
#pragma unroll
        for (int j = 0; j < 8; j++) acc[i][j] = 0.f;

    for (int k0 = 0; k0 < HV; k0 += BK) {
#pragma unroll
        for (int l = 0; l < 2; l++) {
            int s = tid + l * 256;
            int r = s >> 2;
            int kq = s & 3;
            float4 va = *(const float4*)(base + (size_t)(nBase + r) * HV + k0 + kq * 4);
            As[kq * 4 + 0][r] = va.x; As[kq * 4 + 1][r] = va.y;
            As[kq * 4 + 2][r] = va.z; As[kq * 4 + 3][r] = va.w;
            float4 vb = *(const float4*)(base + (size_t)(mBase + r) * HV + k0 + kq * 4);
            Bs[kq * 4 + 0][r] = vb.x; Bs[kq * 4 + 1][r] = vb.y;
            Bs[kq * 4 + 2][r] = vb.z; Bs[kq * 4 + 3][r] = vb.w;
        }
        __syncthreads();
#pragma unroll
        for (int kk = 0; kk < BK; kk++) {
            float a[8], bb[8];
            *(float4*)&a[0] = *(const float4*)&As[kk][ty * 4];
            *(float4*)&a[4] = *(const float4*)&As[kk][64 + ty * 4];
            *(float4*)&bb[0] = *(const float4*)&Bs[kk][tx * 4];
            *(float4*)&bb[4] = *(const float4*)&Bs[kk][64 + tx * 4];
#pragma unroll
            for (int i = 0; i < 8; i++)
#pragma unroll
                for (int j = 0; j < 8; j++)
                    acc[i][j] = fmaf(a[i], bb[j], acc[i][j]);
        }
        __syncthreads();
    }

    // softplus in place (sim values are in [-1,1]: expf/log1pf exact enough)
#pragma unroll
    for (int i = 0; i < 8; i++)
#pragma unroll
        for (int j = 0; j < 8; j++)
            acc[i][j] = log1pf(expf(acc[i][j]));

    // ---- column sums (reduce over n) -> c[b, mBase + col] ----
#pragma unroll
    for (int j = 0; j < 8; j++) {
        float cs = 0.f;
#pragma unroll
        for (int i = 0; i < 8; i++) cs += acc[i][j];
        int col = (j < 4) ? (tx * 4 + j) : (64 + tx * 4 + j - 4);
        red[ty][col] = cs;
    }
    __syncthreads();
    if (tid < 128) {
        float s = 0.f;
#pragma unroll
        for (int t2 = 0; t2 < 16; t2++) s += red[t2][tid];
        atomicAdd(&g_c[b * NV + mBase + tid], s);
    }
    __syncthreads();

    // ---- row sums (reduce over m) -> c[b, nBase + row], off-diagonal only ----
    if (ti != tj) {
#pragma unroll
        for (int i = 0; i < 8; i++) {
            float rs = 0.f;
#pragma unroll
            for (int j = 0; j < 8; j++) rs += acc[i][j];
            int rowl = (i < 4) ? (ty * 4 + i) : (64 + ty * 4 + i - 4);
            red[tx][rowl] = rs;
        }
        __syncthreads();
        if (tid < 128) {
            float s = 0.f;
#pragma unroll
            for (int t2 = 0; t2 < 16; t2++) s += red[t2][tid];
            atomicAdd(&g_c[b * NV + nBase + tid], s);
        }
    }
}

// ============================================================
// witness[b,h] = (1/N) * sum_m c[b,m] * hidden[b,m,h]
// ============================================================
__global__ __launch_bounds__(512)
void witness_kernel()
{
    const int b = blockIdx.x;
    const int h = threadIdx.x;
    __shared__ float cs[NV];
    for (int m = threadIdx.x; m < NV; m += blockDim.x) cs[m] = g_c[b * NV + m];
    __syncthreads();
    float accv = 0.f;
    const float* hp = g_hidden + (size_t)b * NV * HV + h;
    for (int m = 0; m < NV; m++)
        accv = fmaf(cs[m], hp[(size_t)m * HV], accv);
    g_wit[b * HV + h] = accv * (1.0f / NV);
}

// ============================================================
// out[b,g] = witness[b] . Wp[g] + bp[g]
// ============================================================
__global__ __launch_bounds__(512)
void proj_kernel(const float* __restrict__ Wp, const float* __restrict__ bp,
                 float* __restrict__ out)
{
    const int b = blockIdx.x;
    const int g = threadIdx.x;
    __shared__ float w[HV];
    w[g] = g_wit[b * HV + g];
    __syncthreads();
    float accv = bp[g];
    const float* wp = Wp + (size_t)g * HV;
#pragma unroll 8
    for (int h = 0; h < HV; h++)
        accv = fmaf(w[h], wp[h], accv);
    out[b * HV + g] = accv;
}

extern "C" void kernel_launch(void* const* d_in, const int* in_sizes, int n_in,
                              void* d_out, int out_size)
{
    const int*   tokens = (const int*)d_in[0];
    const float* emb    = (const float*)d_in[1];
    const float* W1     = (const float*)d_in[2];
    const float* b1     = (const float*)d_in[3];
    const float* W2     = (const float*)d_in[4];
    const float* b2     = (const float*)d_in[5];
    const float* Wp     = (const float*)d_in[6];
    const float* bp     = (const float*)d_in[7];
    float* out = (float*)d_out;
    (void)in_sizes; (void)n_in; (void)out_size;

    dim3 gGemm(MROWS / BM, HV / BN);      // 128 x 4
    gemm_kernel<0><<<gGemm, 256>>>(emb, tokens, W1, b1);
    gemm_kernel<1><<<gGemm, 256>>>(nullptr, nullptr, W2, b2);
    norm_kernel<<<MROWS, 128>>>();
    zero_c_kernel<<<(BV * NV + 255) / 256, 256>>>();
    sim_kernel<<<dim3(136, BV), 256>>>();
    witness_kernel<<<BV, 512>>>();
    proj_kernel<<<BV, 512>>>(Wp, bp, out);
}

// round 2
// speedup vs baseline: 1.0370x; 1.0370x over previous
#include <cuda_runtime.h>
#include <cstdint>

#define BV 8
#define NV 2048
#define EV 256
#define HV 512
#define MROWS (BV*NV)   // 16384

// ---- scratch (static device globals; no runtime allocation) ----
__device__ float g_h[(size_t)MROWS * HV];       // 32 MB  relu(emb@W1^T+b1)
__device__ float g_hidden[(size_t)MROWS * HV];  // 32 MB  h@W2^T+b2
__device__ float g_norm[(size_t)MROWS * HV];    // 32 MB  row-normalized hidden
__device__ float g_c[BV * NV];                  // column sums of softplus(sim)
__device__ float g_wit[BV * HV];                // witness

constexpr int BM = 128, BN = 128, BK = 16;

// ---- packed f32x2 helpers (sm_100+; ptxas never auto-fuses these) ----
__device__ __forceinline__ void ffma2(unsigned long long& d,
                                      unsigned long long a,
                                      unsigned long long b)
{
    asm("fma.rn.f32x2 %0, %1, %2, %0;" : "+l"(d) : "l"(a), "l"(b));
}
__device__ __forceinline__ unsigned long long bcast2(float x)
{
    unsigned long long r;
    asm("mov.b64 %0, {%1, %1};" : "=l"(r) : "f"(x));
    return r;
}
__device__ __forceinline__ void unpack2(unsigned long long v, float& lo, float& hi)
{
    asm("mov.b64 {%0, %1}, %2;" : "=f"(lo), "=f"(hi) : "l"(v));
}

// ============================================================
// MODE 0: out = relu(gather(emb,tokens) @ W1^T + b1) -> g_h     (K=256)
// MODE 1: out = g_h @ W2^T + b2                      -> g_hidden (K=512)
// 256 threads, 128x128 tile, 8x8 microtile (split-half), f32x2 core.
// ============================================================
template<int MODE>
__global__ __launch_bounds__(256)
void gemm_kernel(const float* __restrict__ Aext, const int* __restrict__ tokens,
                 const float* __restrict__ W, const float* __restrict__ bias)
{
    constexpr int KD = (MODE == 0) ? EV : HV;
    __shared__ float As[BK][BM];
    __shared__ float Bs[BK][BN];
    __shared__ const float* rowPtr[BM];

    const int tid = threadIdx.x;
    const int rowBase = blockIdx.x * BM;
    const int colBase = blockIdx.y * BN;

    if (tid < BM) {
        int r = rowBase + tid;
        if (MODE == 0) rowPtr[tid] = Aext + (size_t)tokens[r] * EV;
        else           rowPtr[tid] = g_h + (size_t)r * HV;
    }
    __syncthreads();

    const int tx = tid & 15, ty = tid >> 4;
    unsigned long long acc2[8][4];
#pragma unroll
    for (int i = 0; i < 8; i++)
#pragma unroll
        for (int p = 0; p < 4; p++) acc2[i][p] = 0ULL;

    for (int k0 = 0; k0 < KD; k0 += BK) {
#pragma unroll
        for (int l = 0; l < 2; l++) {
            int s = tid + l * 256;
            int r = s >> 2;
            int kq = s & 3;
            float4 v = *(const float4*)(rowPtr[r] + k0 + kq * 4);
            As[kq * 4 + 0][r] = v.x; As[kq * 4 + 1][r] = v.y;
            As[kq * 4 + 2][r] = v.z; As[kq * 4 + 3][r] = v.w;
        }
#pragma unroll
        for (int l = 0; l < 2; l++) {
            int s = tid + l * 256;
            int r = s >> 2;
            int kq = s & 3;
            float4 v = *(const float4*)(W + (size_t)(colBase + r) * KD + k0 + kq * 4);
            Bs[kq * 4 + 0][r] = v.x; Bs[kq * 4 + 1][r] = v.y;
            Bs[kq * 4 + 2][r] = v.z; Bs[kq * 4 + 3][r] = v.w;
        }
        __syncthreads();
#pragma unroll
        for (int kk = 0; kk < BK; kk++) {
            float a[8];
            *(float4*)&a[0] = *(const float4*)&As[kk][ty * 4];
            *(float4*)&a[4] = *(const float4*)&As[kk][64 + ty * 4];
            ulonglong2 bl = *(const ulonglong2*)&Bs[kk][tx * 4];
            ulonglong2 bh = *(const ulonglong2*)&Bs[kk][64 + tx * 4];
#pragma unroll
            for (int i = 0; i < 8; i++) {
                unsigned long long av = bcast2(a[i]);
                ffma2(acc2[i][0], av, bl.x);
                ffma2(acc2[i][1], av, bl.y);
                ffma2(acc2[i][2], av, bh.x);
                ffma2(acc2[i][3], av, bh.y);
            }
        }
        __syncthreads();
    }

    float* outp = (MODE == 0) ? g_h : g_hidden;
#pragma unroll
    for (int i = 0; i < 8; i++) {
        int rl = (i < 4) ? (ty * 4 + i) : (64 + ty * 4 + i - 4);
        size_t rowOff = (size_t)(rowBase + rl) * HV;
#pragma unroll
        for (int jh = 0; jh < 2; jh++) {
            int c = colBase + (jh ? (64 + tx * 4) : (tx * 4));
            float4 o;
            unpack2(acc2[i][jh * 2 + 0], o.x, o.y);
            unpack2(acc2[i][jh * 2 + 1], o.z, o.w);
            o.x += bias[c + 0]; o.y += bias[c + 1];
            o.z += bias[c + 2]; o.w += bias[c + 3];
            if (MODE == 0) {
                o.x = fmaxf(o.x, 0.f); o.y = fmaxf(o.y, 0.f);
                o.z = fmaxf(o.z, 0.f); o.w = fmaxf(o.w, 0.f);
            }
            *(float4*)(outp + rowOff + c) = o;
        }
    }
}

// ============================================================
// Row-normalize: g_norm[r] = g_hidden[r] / max(||g_hidden[r]||, 1e-12)
// ============================================================
__global__ __launch_bounds__(128)
void norm_kernel()
{
    const int row = blockIdx.x;
    const int t = threadIdx.x;
    const float4 x = ((const float4*)(g_hidden + (size_t)row * HV))[t];
    float ss = x.x * x.x + x.y * x.y + x.z * x.z + x.w * x.w;
#pragma unroll
    for (int o = 16; o; o >>= 1) ss += __shfl_xor_sync(0xffffffffu, ss, o);
    __shared__ float wsum[4];
    if ((t & 31) == 0) wsum[t >> 5] = ss;
    __syncthreads();
    float tot = wsum[0] + wsum[1] + wsum[2] + wsum[3];
    float inv = 1.0f / fmaxf(sqrtf(tot), 1e-12f);
    float4 o4 = make_float4(x.x * inv, x.y * inv, x.z * inv, x.w * inv);
    ((float4*)(g_norm + (size_t)row * HV))[t] = o4;
}

__global__ void zero_c_kernel()
{
    int i = blockIdx.x * blockDim.x + threadIdx.x;
    if (i < BV * NV) g_c[i] = 0.f;
}

// ============================================================
// Triangular sim tiles with dual reduction, f32x2 core.
// Grid: (136, B).
// ============================================================
__global__ __launch_bounds__(256)
void sim_kernel()
{
    const int b = blockIdx.y;
    int rem = blockIdx.x, ti = 0;
    while (rem >= (16 - ti)) { rem -= (16 - ti); ti++; }
    const int tj = ti + rem;
    const int nBase = ti * BM;
    const int mBase = tj * BN;
    const float* base = g_norm + (size_t)b * NV * HV;

    __shared__ float As[BK][BM];
    __shared__ float Bs[BK][BN];
    __shared__ float red[16][128];

    const int tid = threadIdx.x;
    const int tx = tid & 15, ty = tid >> 4;

    unsigned long long acc2[8][4];
#pragma unroll
    for (int i = 0; i < 8; i++)
#pragma unroll
        for (int p = 0; p < 4; p++) acc2[i][p] = 0ULL;

    for (int k0 = 0; k0 < HV; k0 += BK) {
#pragma unroll
        for (int l = 0; l < 2; l++) {
            int s = tid + l * 256;
            int r = s >> 2;
            int kq = s & 3;
            float4 va = *(const float4*)(base + (size_t)(nBase + r) * HV + k0 + kq * 4);
            As[kq * 4 + 0][r] = va.x; As[kq * 4 + 1][r] = va.y;
            As[kq * 4 + 2][r] = va.z; As[kq * 4 + 3][r] = va.w;
            float4 vb = *(const float4*)(base + (size_t)(mBase + r) * HV + k0 + kq * 4);
            Bs[kq * 4 + 0][r] = vb.x; Bs[kq * 4 + 1][r] = vb.y;
            Bs[kq * 4 + 2][r] = vb.z; Bs[kq * 4 + 3][r] = vb.w;
        }
        __syncthreads();
#pragma unroll
        for (int kk = 0; kk < BK; kk++) {
            float a[8];
            *(float4*)&a[0] = *(const float4*)&As[kk][ty * 4];
            *(float4*)&a[4] = *(const float4*)&As[kk][64 + ty * 4];
            ulonglong2 bl = *(const ulonglong2*)&Bs[kk][tx * 4];
            ulonglong2 bh = *(const ulonglong2*)&Bs[kk][64 + tx * 4];
#pragma unroll
            for (int i = 0; i < 8; i++) {
                unsigned long long av = bcast2(a[i]);
                ffma2(acc2[i][0], av, bl.x);
                ffma2(acc2[i][1], av, bl.y);
                ffma2(acc2[i][2], av, bh.x);
                ffma2(acc2[i][3], av, bh.y);
            }
        }
        __syncthreads();
    }

    // unpack + softplus (sim in [-1,1]: expf/log1pf exact enough)
    float acc[8][8];
#pragma unroll
    for (int i = 0; i < 8; i++)
#pragma unroll
        for (int p = 0; p < 4; p++) {
            float lo, hi;
            unpack2(acc2[i][p], lo, hi);
            acc[i][p * 2 + 0] = log1pf(expf(lo));
            acc[i][p * 2 + 1] = log1pf(expf(hi));
        }

    // ---- column sums (reduce over n) -> c[b, mBase + col] ----
#pragma unroll
    for (int j = 0; j < 8; j++) {
        float cs = 0.f;
#pragma unroll
        for (int i = 0; i < 8; i++) cs += acc[i][j];
        int col = (j < 4) ? (tx * 4 + j) : (64 + tx * 4 + j - 4);
        red[ty][col] = cs;
    }
    __syncthreads();
    if (tid < 128) {
        float s = 0.f;
#pragma unroll
        for (int t2 = 0; t2 < 16; t2++) s += red[t2][tid];
        atomicAdd(&g_c[b * NV + mBase + tid], s);
    }
    __syncthreads();

    // ---- row sums (reduce over m) -> c[b, nBase + row], off-diagonal only ----
    if (ti != tj) {
#pragma unroll
        for (int i = 0; i < 8; i++) {
            float rs = 0.f;
#pragma unroll
            for (int j = 0; j < 8; j++) rs += acc[i][j];
            int rowl = (i < 4) ? (ty * 4 + i) : (64 + ty * 4 + i - 4);
            red[tx][rowl] = rs;
        }
        __syncthreads();
        if (tid < 128) {
            float s = 0.f;
#pragma unroll
            for (int t2 = 0; t2 < 16; t2++) s += red[t2][tid];
            atomicAdd(&g_c[b * NV + nBase + tid], s);
        }
    }
}

// ============================================================
// witness[b,h] = (1/N) * sum_m c[b,m] * hidden[b,m,h]
// ============================================================
__global__ __launch_bounds__(512)
void witness_kernel()
{
    const int b = blockIdx.x;
    const int h = threadIdx.x;
    __shared__ float cs[NV];
    for (int m = threadIdx.x; m < NV; m += blockDim.x) cs[m] = g_c[b * NV + m];
    __syncthreads();
    float accv = 0.f;
    const float* hp = g_hidden + (size_t)b * NV * HV + h;
    for (int m = 0; m < NV; m++)
        accv = fmaf(cs[m], hp[(size_t)m * HV], accv);
    g_wit[b * HV + h] = accv * (1.0f / NV);
}

// ============================================================
// out[b,g] = witness[b] . Wp[g] + bp[g]
// ============================================================
__global__ __launch_bounds__(512)
void proj_kernel(const float* __restrict__ Wp, const float* __restrict__ bp,
                 float* __restrict__ out)
{
    const int b = blockIdx.x;
    const int g = threadIdx.x;
    __shared__ float w[HV];
    w[g] = g_wit[b * HV + g];
    __syncthreads();
    float accv = bp[g];
    const float* wp = Wp + (size_t)g * HV;
#pragma unroll 8
    for (int h = 0; h < HV; h++)
        accv = fmaf(w[h], wp[h], accv);
    out[b * HV + g] = accv;
}

extern "C" void kernel_launch(void* const* d_in, const int* in_sizes, int n_in,
                              void* d_out, int out_size)
{
    const int*   tokens = (const int*)d_in[0];
    const float* emb    = (const float*)d_in[1];
    const float* W1     = (const float*)d_in[2];
    const float* b1     = (const float*)d_in[3];
    const float* W2     = (const float*)d_in[4];
    const float* b2     = (const float*)d_in[5];
    const float* Wp     = (const float*)d_in[6];
    const float* bp     = (const float*)d_in[7];
    float* out = (float*)d_out;
    (void)in_sizes; (void)n_in; (void)out_size;

    dim3 gGemm(MROWS / BM, HV / BN);      // 128 x 4
    gemm_kernel<0><<<gGemm, 256>>>(emb, tokens, W1, b1);
    gemm_kernel<1><<<gGemm, 256>>>(nullptr, nullptr, W2, b2);
    norm_kernel<<<MROWS, 128>>>();
    zero_c_kernel<<<(BV * NV + 255) / 256, 256>>>();
    sim_kernel<<<dim3(136, BV), 256>>>();
    witness_kernel<<<BV, 512>>>();
    proj_kernel<<<BV, 512>>>(Wp, bp, out);
}

// round 5
// speedup vs baseline: 2.0014x; 1.9301x over previous
#include <cuda_runtime.h>
#include <cuda_bf16.h>
#include <cstdint>

#define BV 8
#define NV 2048
#define EV 256
#define HV 512
#define MROWS (BV*NV)   // 16384

// ---------------- scratch (static device globals) ----------------
__device__ __nv_bfloat16 g_A1hi[(size_t)MROWS * EV];
__device__ __nv_bfloat16 g_A1lo[(size_t)MROWS * EV];
__device__ __nv_bfloat16 g_W1hi[HV * EV];
__device__ __nv_bfloat16 g_W1lo[HV * EV];
__device__ __nv_bfloat16 g_W2hi[HV * HV];
__device__ __nv_bfloat16 g_W2lo[HV * HV];
__device__ __nv_bfloat16 g_hHi[(size_t)MROWS * HV];
__device__ __nv_bfloat16 g_hLo[(size_t)MROWS * HV];
__device__ float         g_hidden[(size_t)MROWS * HV];   // fp32, for witness
__device__ __nv_bfloat16 g_nHi[(size_t)MROWS * HV];
__device__ __nv_bfloat16 g_nLo[(size_t)MROWS * HV];
__device__ float g_c[BV * NV];
__device__ float g_wit[BV * HV];

// ---------------- helpers ----------------
__device__ __forceinline__ uint32_t smem_u32(const void* p) {
    uint32_t a;
    asm("{ .reg .u64 t; cvta.to.shared.u64 t, %1; cvt.u32.u64 %0, t; }" : "=r"(a) : "l"(p));
    return a;
}
__device__ __forceinline__ void mma_bf16(float* c, const uint32_t* a, const uint32_t* b) {
    asm volatile("mma.sync.aligned.m16n8k16.row.col.f32.bf16.bf16.f32 "
                 "{%0,%1,%2,%3}, {%4,%5,%6,%7}, {%8,%9}, {%0,%1,%2,%3};"
                 : "+f"(c[0]), "+f"(c[1]), "+f"(c[2]), "+f"(c[3])
                 : "r"(a[0]), "r"(a[1]), "r"(a[2]), "r"(a[3]),
                   "r"(b[0]), "r"(b[1]));
}
#define LDSM4(r0, r1, r2, r3, addr) \
    asm volatile("ldmatrix.sync.aligned.m8n8.x4.shared.b16 {%0,%1,%2,%3}, [%4];" \
                 : "=r"(r0), "=r"(r1), "=r"(r2), "=r"(r3) : "r"(addr))
#define CP_COMMIT asm volatile("cp.async.commit_group;" ::: "memory")
#define CP_WAIT1  asm volatile("cp.async.wait_group 1;" ::: "memory")

// ---------------- conversion kernels ----------------
__global__ __launch_bounds__(64)
void conv_emb_kernel(const int* __restrict__ tokens, const float* __restrict__ emb)
{
    const int row = blockIdx.x;
    const int t = threadIdx.x;
    const int tok = tokens[row];
    float4 v = *(const float4*)(emb + (size_t)tok * EV + t * 4);
    float vv[4] = {v.x, v.y, v.z, v.w};
    __nv_bfloat16 h[4], l[4];
#pragma unroll
    for (int i = 0; i < 4; i++) {
        h[i] = __float2bfloat16(vv[i]);
        l[i] = __float2bfloat16(vv[i] - __bfloat162float(h[i]));
    }
    size_t o = (size_t)row * EV + t * 4;
    *(__nv_bfloat162*)(g_A1hi + o)     = __nv_bfloat162(h[0], h[1]);
    *(__nv_bfloat162*)(g_A1hi + o + 2) = __nv_bfloat162(h[2], h[3]);
    *(__nv_bfloat162*)(g_A1lo + o)     = __nv_bfloat162(l[0], l[1]);
    *(__nv_bfloat162*)(g_A1lo + o + 2) = __nv_bfloat162(l[2], l[3]);
}

// WHICH = 0 -> W1 (n4 = HV*EV/4), WHICH = 1 -> W2 (n4 = HV*HV/4).
// Destinations referenced in DEVICE code only (host must never pass __device__ symbols).
template<int WHICH>
__global__ __launch_bounds__(256)
void conv_split_kernel(const float* __restrict__ src)
{
    constexpr int n4 = (WHICH == 0) ? (HV * EV / 4) : (HV * HV / 4);
    __nv_bfloat16* hi = (WHICH == 0) ? g_W1hi : g_W2hi;
    __nv_bfloat16* lo = (WHICH == 0) ? g_W1lo : g_W2lo;
    int i = blockIdx.x * blockDim.x + threadIdx.x;
    if (i >= n4) return;
    float4 v = ((const float4*)src)[i];
    float vv[4] = {v.x, v.y, v.z, v.w};
    __nv_bfloat16 h[4], l[4];
#pragma unroll
    for (int k = 0; k < 4; k++) {
        h[k] = __float2bfloat16(vv[k]);
        l[k] = __float2bfloat16(vv[k] - __bfloat162float(h[k]));
    }
    size_t o = (size_t)i * 4;
    *(__nv_bfloat162*)(hi + o)     = __nv_bfloat162(h[0], h[1]);
    *(__nv_bfloat162*)(hi + o + 2) = __nv_bfloat162(h[2], h[3]);
    *(__nv_bfloat162*)(lo + o)     = __nv_bfloat162(l[0], l[1]);
    *(__nv_bfloat162*)(lo + o + 2) = __nv_bfloat162(l[2], l[3]);
}

// ============================================================
// Tensor-core GEMM via warp mma.sync (bf16 2-term split, 3 passes).
// MODE 0: relu(A1 @ W1^T + b1) -> g_hHi/Lo         (K=256)
// MODE 1: h @ W2^T + b2        -> g_hidden (fp32)  (K=512)
// MODE 2: triangular sim tiles -> softplus -> g_c  (K=512)
// 256 threads = 8 warps (2M x 4N), warp tile 64x32, block tile 128x128, BK=64.
// cp.async double buffering: 2 stages x 4 tiles x 16KB = 128KB smem.
// ============================================================
constexpr int STAGE_BYTES = 4 * 16384;
constexpr int SMEM_SZ = 2 * STAGE_BYTES;   // 128 KB

template<int MODE>
__global__ __launch_bounds__(256)
void gemm_t(const float* __restrict__ bias)
{
    constexpr int KDIM = (MODE == 0) ? EV : HV;
    constexpr int NC = KDIM / 64;
    extern __shared__ __align__(1024) char smem[];
    const uint32_t sbase = smem_u32(smem);
    __shared__ float sBias[128];

    const int tid = threadIdx.x;
    const int lane = tid & 31;
    const int wid = tid >> 5;

    int rowA, rowB, bIdx = 0, ti = 0, tj = 0;
    if (MODE == 2) {
        bIdx = blockIdx.y;
        int rem = blockIdx.x;
        while (rem >= (16 - ti)) { rem -= (16 - ti); ti++; }
        tj = ti + rem;
        rowA = bIdx * NV + ti * 128;
        rowB = bIdx * NV + tj * 128;
    } else {
        rowA = blockIdx.x * 128;
        rowB = blockIdx.y * 128;
    }

    const __nv_bfloat16* srcs[4];
    if (MODE == 0) {
        srcs[0] = g_A1hi + (size_t)rowA * KDIM; srcs[1] = g_A1lo + (size_t)rowA * KDIM;
        srcs[2] = g_W1hi + (size_t)rowB * KDIM; srcs[3] = g_W1lo + (size_t)rowB * KDIM;
    } else if (MODE == 1) {
        srcs[0] = g_hHi + (size_t)rowA * KDIM;  srcs[1] = g_hLo + (size_t)rowA * KDIM;
        srcs[2] = g_W2hi + (size_t)rowB * KDIM; srcs[3] = g_W2lo + (size_t)rowB * KDIM;
    } else {
        srcs[0] = g_nHi + (size_t)rowA * KDIM;  srcs[1] = g_nLo + (size_t)rowA * KDIM;
        srcs[2] = g_nHi + (size_t)rowB * KDIM;  srcs[3] = g_nLo + (size_t)rowB * KDIM;
    }
    if (MODE < 2 && tid < 128) sBias[tid] = bias[blockIdx.y * 128 + tid];

    // ---- stage loader (cp.async, SW128-style xor swizzle on 128B rows) ----
    auto load_stage = [&](int stage, int c) {
        const uint32_t stBase = sbase + stage * STAGE_BYTES;
        const int k0 = c * 64;
#pragma unroll
        for (int comp = 0; comp < 4; comp++) {
            const __nv_bfloat16* src = srcs[comp] + k0;
            const uint32_t dstT = stBase + comp * 16384;
#pragma unroll
            for (int l = 0; l < 4; l++) {
                int s = l * 256 + tid;
                int r = s >> 3, seg = s & 7;
                uint32_t off = (uint32_t)(r * 128 + seg * 16);
                uint32_t dst = dstT + (off ^ ((off >> 3) & 0x70));
                const void* gsrc = src + (size_t)r * KDIM + seg * 8;
                asm volatile("cp.async.cg.shared.global [%0], [%1], 16;"
                             :: "r"(dst), "l"(gsrc));
            }
        }
    };

    // ---- per-thread fragment addressing ----
    const int warpM = (wid >> 2) * 64;
    const int warpN = (wid & 3) * 32;
    const uint32_t xorT = (uint32_t)((lane & 7) << 4);
    uint32_t aRow[4], bRow[2];
#pragma unroll
    for (int mi = 0; mi < 4; mi++)
        aRow[mi] = (uint32_t)((warpM + mi * 16 + (lane & 15)) * 128);
    const int bLocal = (lane & 7) + ((lane >> 4) << 3);
#pragma unroll
    for (int p = 0; p < 2; p++)
        bRow[p] = (uint32_t)((warpN + p * 16 + bLocal) * 128);
    const uint32_t aKsel = (uint32_t)((lane >> 4) << 4);
    const uint32_t bKsel = (uint32_t)(((lane >> 3) & 1) << 4);

    float acc[4][4][4];
#pragma unroll
    for (int mi = 0; mi < 4; mi++)
#pragma unroll
        for (int ni = 0; ni < 4; ni++)
#pragma unroll
            for (int k = 0; k < 4; k++) acc[mi][ni][k] = 0.f;

    auto compute_stage = [&](int stage) {
        const uint32_t stBase = sbase + stage * STAGE_BYTES;
        const uint32_t tAhi = stBase, tAlo = stBase + 16384;
        const uint32_t tBhi = stBase + 32768, tBlo = stBase + 49152;
#pragma unroll
        for (int ks = 0; ks < 4; ks++) {
            const uint32_t kA = ((uint32_t)(ks * 32) + aKsel) ^ xorT;
            const uint32_t kB = ((uint32_t)(ks * 32) + bKsel) ^ xorT;
            uint32_t bh[4][2], bl[4][2];
            {
                uint32_t r0, r1, r2, r3;
                LDSM4(r0, r1, r2, r3, tBhi + bRow[0] + kB);
                bh[0][0] = r0; bh[0][1] = r1; bh[1][0] = r2; bh[1][1] = r3;
                LDSM4(r0, r1, r2, r3, tBhi + bRow[1] + kB);
                bh[2][0] = r0; bh[2][1] = r1; bh[3][0] = r2; bh[3][1] = r3;
                LDSM4(r0, r1, r2, r3, tBlo + bRow[0] + kB);
                bl[0][0] = r0; bl[0][1] = r1; bl[1][0] = r2; bl[1][1] = r3;
                LDSM4(r0, r1, r2, r3, tBlo + bRow[1] + kB);
                bl[2][0] = r0; bl[2][1] = r1; bl[3][0] = r2; bl[3][1] = r3;
            }
            uint32_t a[4][4];
#pragma unroll
            for (int mi = 0; mi < 4; mi++)
                LDSM4(a[mi][0], a[mi][1], a[mi][2], a[mi][3], tAhi + aRow[mi] + kA);
            // pass 1: Ahi * Bhi
#pragma unroll
            for (int mi = 0; mi < 4; mi++)
#pragma unroll
                for (int ni = 0; ni < 4; ni++)
                    mma_bf16(acc[mi][ni], a[mi], bh[ni]);
            // pass 2: Ahi * Blo
#pragma unroll
            for (int mi = 0; mi < 4; mi++)
#pragma unroll
                for (int ni = 0; ni < 4; ni++)
                    mma_bf16(acc[mi][ni], a[mi], bl[ni]);
            // pass 3: Alo * Bhi
#pragma unroll
            for (int mi = 0; mi < 4; mi++)
                LDSM4(a[mi][0], a[mi][1], a[mi][2], a[mi][3], tAlo + aRow[mi] + kA);
#pragma unroll
            for (int mi = 0; mi < 4; mi++)
#pragma unroll
                for (int ni = 0; ni < 4; ni++)
                    mma_bf16(acc[mi][ni], a[mi], bh[ni]);
        }
    };

    // ---- pipelined mainloop ----
    load_stage(0, 0); CP_COMMIT;
    load_stage(1, 1); CP_COMMIT;
    for (int c = 0; c < NC; c++) {
        CP_WAIT1;
        __syncthreads();
        compute_stage(c & 1);
        __syncthreads();
        if (c + 2 < NC) load_stage(c & 1, c + 2);
        CP_COMMIT;
    }

    // ---- epilogue ----
    const int rBase0 = warpM + (lane >> 2);
    const int cBase = warpN + (lane & 3) * 2;

    if (MODE < 2) {
#pragma unroll
        for (int mi = 0; mi < 4; mi++) {
            const int r = rBase0 + mi * 16;
#pragma unroll
            for (int ni = 0; ni < 4; ni++) {
                const int cl = cBase + ni * 8;
                const int gc = blockIdx.y * 128 + cl;
                float v0 = acc[mi][ni][0] + sBias[cl];
                float v1 = acc[mi][ni][1] + sBias[cl + 1];
                float v2 = acc[mi][ni][2] + sBias[cl];
                float v3 = acc[mi][ni][3] + sBias[cl + 1];
                if (MODE == 1) {
                    *(float2*)(g_hidden + (size_t)(rowA + r) * HV + gc) = make_float2(v0, v1);
                    *(float2*)(g_hidden + (size_t)(rowA + r + 8) * HV + gc) = make_float2(v2, v3);
                } else {
                    v0 = fmaxf(v0, 0.f); v1 = fmaxf(v1, 0.f);
                    v2 = fmaxf(v2, 0.f); v3 = fmaxf(v3, 0.f);
                    __nv_bfloat16 h0 = __float2bfloat16(v0), h1 = __float2bfloat16(v1);
                    __nv_bfloat16 h2 = __float2bfloat16(v2), h3 = __float2bfloat16(v3);
                    __nv_bfloat16 l0 = __float2bfloat16(v0 - __bfloat162float(h0));
                    __nv_bfloat16 l1 = __float2bfloat16(v1 - __bfloat162float(h1));
                    __nv_bfloat16 l2 = __float2bfloat16(v2 - __bfloat162float(h2));
                    __nv_bfloat16 l3 = __float2bfloat16(v3 - __bfloat162float(h3));
                    size_t o0 = (size_t)(rowA + r) * HV + gc;
                    size_t o1 = (size_t)(rowA + r + 8) * HV + gc;
                    *(__nv_bfloat162*)(g_hHi + o0) = __nv_bfloat162(h0, h1);
                    *(__nv_bfloat162*)(g_hHi + o1) = __nv_bfloat162(h2, h3);
                    *(__nv_bfloat162*)(g_hLo + o0) = __nv_bfloat162(l0, l1);
                    *(__nv_bfloat162*)(g_hLo + o1) = __nv_bfloat162(l2, l3);
                }
            }
        }
    } else {
        // sim epilogue: softplus, dual reduction via smem atomics
        float* rowAcc = (float*)smem;          // [128]
        float* colAcc = (float*)smem + 128;    // [128]
        if (tid < 256) ((float*)smem)[tid] = 0.f;
        __syncthreads();

        float rowPart[4][2];
        float colPart[4][2];
#pragma unroll
        for (int i = 0; i < 4; i++) {
            rowPart[i][0] = rowPart[i][1] = 0.f;
            colPart[i][0] = colPart[i][1] = 0.f;
        }
#pragma unroll
        for (int mi = 0; mi < 4; mi++)
#pragma unroll
            for (int ni = 0; ni < 4; ni++) {
                float v0 = log1pf(expf(acc[mi][ni][0]));
                float v1 = log1pf(expf(acc[mi][ni][1]));
                float v2 = log1pf(expf(acc[mi][ni][2]));
                float v3 = log1pf(expf(acc[mi][ni][3]));
                rowPart[mi][0] += v0 + v1;
                rowPart[mi][1] += v2 + v3;
                colPart[ni][0] += v0 + v2;
                colPart[ni][1] += v1 + v3;
            }
#pragma unroll
        for (int mi = 0; mi < 4; mi++) {
            atomicAdd(&rowAcc[rBase0 + mi * 16], rowPart[mi][0]);
            atomicAdd(&rowAcc[rBase0 + mi * 16 + 8], rowPart[mi][1]);
        }
#pragma unroll
        for (int ni = 0; ni < 4; ni++) {
            atomicAdd(&colAcc[cBase + ni * 8], colPart[ni][0]);
            atomicAdd(&colAcc[cBase + ni * 8 + 1], colPart[ni][1]);
        }
        __syncthreads();
        if (tid < 128) {
            atomicAdd(&g_c[bIdx * NV + tj * 128 + tid], colAcc[tid]);
            if (ti != tj)
                atomicAdd(&g_c[bIdx * NV + ti * 128 + tid], rowAcc[tid]);
        }
    }
}

// ---------------- normalize -> bf16 hi/lo ----------------
__global__ __launch_bounds__(128)
void norm_kernel()
{
    const int row = blockIdx.x;
    const int t = threadIdx.x;
    const float4 x = ((const float4*)(g_hidden + (size_t)row * HV))[t];
    float ss = x.x * x.x + x.y * x.y + x.z * x.z + x.w * x.w;
#pragma unroll
    for (int o = 16; o; o >>= 1) ss += __shfl_xor_sync(0xffffffffu, ss, o);
    __shared__ float wsum[4];
    if ((t & 31) == 0) wsum[t >> 5] = ss;
    __syncthreads();
    float tot = wsum[0] + wsum[1] + wsum[2] + wsum[3];
    float inv = 1.0f / fmaxf(sqrtf(tot), 1e-12f);
    float vv[4] = {x.x * inv, x.y * inv, x.z * inv, x.w * inv};
    __nv_bfloat16 h[4], l[4];
#pragma unroll
    for (int i = 0; i < 4; i++) {
        h[i] = __float2bfloat16(vv[i]);
        l[i] = __float2bfloat16(vv[i] - __bfloat162float(h[i]));
    }
    size_t o = (size_t)row * HV + t * 4;
    *(__nv_bfloat162*)(g_nHi + o)     = __nv_bfloat162(h[0], h[1]);
    *(__nv_bfloat162*)(g_nHi + o + 2) = __nv_bfloat162(h[2], h[3]);
    *(__nv_bfloat162*)(g_nLo + o)     = __nv_bfloat162(l[0], l[1]);
    *(__nv_bfloat162*)(g_nLo + o + 2) = __nv_bfloat162(l[2], l[3]);
}

__global__ void zero_kernel()
{
    int i = blockIdx.x * blockDim.x + threadIdx.x;
    if (i < BV * NV) g_c[i] = 0.f;
    if (i < BV * HV) g_wit[i] = 0.f;
}

// ---------------- witness: partial sums over m-chunks ----------------
__global__ __launch_bounds__(512)
void witness_kernel()
{
    const int chunk = blockIdx.x;   // 32 chunks of 64 rows
    const int b = blockIdx.y;
    const int h = threadIdx.x;
    __shared__ float cs[64];
    if (threadIdx.x < 64) cs[threadIdx.x] = g_c[b * NV + chunk * 64 + threadIdx.x];
    __syncthreads();
    const float* hp = g_hidden + (size_t)(b * NV + chunk * 64) * HV + h;
    float a = 0.f;
#pragma unroll 8
    for (int m = 0; m < 64; m++)
        a = fmaf(cs[m], hp[(size_t)m * HV], a);
    atomicAdd(&g_wit[b * HV + h], a);
}

// ---------------- output projection ----------------
__global__ __launch_bounds__(512)
void proj_kernel(const float* __restrict__ Wp, const float* __restrict__ bp,
                 float* __restrict__ out)
{
    const int b = blockIdx.x;
    const int g = threadIdx.x;
    __shared__ float w[HV];
    w[g] = g_wit[b * HV + g] * (1.0f / NV);
    __syncthreads();
    float accv = bp[g];
    const float* wp = Wp + (size_t)g * HV;
#pragma unroll 8
    for (int h = 0; h < HV; h++)
        accv = fmaf(w[h], wp[h], accv);
    out[b * HV + g] = accv;
}

extern "C" void kernel_launch(void* const* d_in, const int* in_sizes, int n_in,
                              void* d_out, int out_size)
{
    const int*   tokens = (const int*)d_in[0];
    const float* emb    = (const float*)d_in[1];
    const float* W1     = (const float*)d_in[2];
    const float* b1     = (const float*)d_in[3];
    const float* W2     = (const float*)d_in[4];
    const float* b2     = (const float*)d_in[5];
    const float* Wp     = (const float*)d_in[6];
    const float* bp     = (const float*)d_in[7];
    float* out = (float*)d_out;
    (void)in_sizes; (void)n_in; (void)out_size;

    cudaFuncSetAttribute(gemm_t<0>, cudaFuncAttributeMaxDynamicSharedMemorySize, SMEM_SZ);
    cudaFuncSetAttribute(gemm_t<1>, cudaFuncAttributeMaxDynamicSharedMemorySize, SMEM_SZ);
    cudaFuncSetAttribute(gemm_t<2>, cudaFuncAttributeMaxDynamicSharedMemorySize, SMEM_SZ);

    conv_emb_kernel<<<MROWS, 64>>>(tokens, emb);
    conv_split_kernel<0><<<(HV * EV / 4 + 255) / 256, 256>>>(W1);
    conv_split_kernel<1><<<(HV * HV / 4 + 255) / 256, 256>>>(W2);

    gemm_t<0><<<dim3(MROWS / 128, HV / 128), 256, SMEM_SZ>>>(b1);
    gemm_t<1><<<dim3(MROWS / 128, HV / 128), 256, SMEM_SZ>>>(b2);

    norm_kernel<<<MROWS, 128>>>();
    zero_kernel<<<(BV * NV + 255) / 256, 256>>>();

    gemm_t<2><<<dim3(136, BV), 256, SMEM_SZ>>>(nullptr);

    witness_kernel<<<dim3(32, BV), 512>>>();
    proj_kernel<<<BV, 512>>>(Wp, bp, out);
}

// round 6
// speedup vs baseline: 2.1776x; 1.0880x over previous
#include <cuda_runtime.h>
#include <cuda_bf16.h>
#include <cstdint>

#define BV 8
#define NV 2048
#define EV 256
#define HV 512
#define MROWS (BV*NV)   // 16384

// ---------------- scratch (static device globals) ----------------
__device__ __nv_bfloat16 g_A1hi[(size_t)MROWS * EV];
__device__ __nv_bfloat16 g_A1lo[(size_t)MROWS * EV];
__device__ __nv_bfloat16 g_W1hi[HV * EV];
__device__ __nv_bfloat16 g_W1lo[HV * EV];
__device__ __nv_bfloat16 g_W2hi[HV * HV];
__device__ __nv_bfloat16 g_W2lo[HV * HV];
__device__ __nv_bfloat16 g_hHi[(size_t)MROWS * HV];
__device__ __nv_bfloat16 g_hLo[(size_t)MROWS * HV];
__device__ float         g_hidden[(size_t)MROWS * HV];   // fp32, for witness
__device__ __nv_bfloat16 g_nHi[(size_t)MROWS * HV];
__device__ __nv_bfloat16 g_nLo[(size_t)MROWS * HV];
__device__ float g_c[BV * NV];
__device__ float g_wit[BV * HV];

// ---------------- helpers ----------------
__device__ __forceinline__ uint32_t smem_u32(const void* p) {
    uint32_t a;
    asm("{ .reg .u64 t; cvta.to.shared.u64 t, %1; cvt.u32.u64 %0, t; }" : "=r"(a) : "l"(p));
    return a;
}
__device__ __forceinline__ void mma_bf16(float* c, const uint32_t* a, const uint32_t* b) {
    asm volatile("mma.sync.aligned.m16n8k16.row.col.f32.bf16.bf16.f32 "
                 "{%0,%1,%2,%3}, {%4,%5,%6,%7}, {%8,%9}, {%0,%1,%2,%3};"
                 : "+f"(c[0]), "+f"(c[1]), "+f"(c[2]), "+f"(c[3])
                 : "r"(a[0]), "r"(a[1]), "r"(a[2]), "r"(a[3]),
                   "r"(b[0]), "r"(b[1]));
}
#define LDSM4(r0, r1, r2, r3, addr) \
    asm volatile("ldmatrix.sync.aligned.m8n8.x4.shared.b16 {%0,%1,%2,%3}, [%4];" \
                 : "=r"(r0), "=r"(r1), "=r"(r2), "=r"(r3) : "r"(addr))
#define CP_COMMIT asm volatile("cp.async.commit_group;" ::: "memory")
#define CP_WAIT1  asm volatile("cp.async.wait_group 1;" ::: "memory")

// ---------------- conversion kernels ----------------
__global__ __launch_bounds__(256)
void conv_emb_kernel(const int* __restrict__ tokens, const float* __restrict__ emb)
{
    const int idx = blockIdx.x * 256 + threadIdx.x;   // one float4 per thread
    const int row = idx >> 6;                         // 64 quads per row
    const int t = idx & 63;
    const int tok = tokens[row];
    float4 v = *(const float4*)(emb + (size_t)tok * EV + t * 4);
    float vv[4] = {v.x, v.y, v.z, v.w};
    __nv_bfloat16 h[4], l[4];
#pragma unroll
    for (int i = 0; i < 4; i++) {
        h[i] = __float2bfloat16(vv[i]);
        l[i] = __float2bfloat16(vv[i] - __bfloat162float(h[i]));
    }
    size_t o = (size_t)row * EV + t * 4;
    *(__nv_bfloat162*)(g_A1hi + o)     = __nv_bfloat162(h[0], h[1]);
    *(__nv_bfloat162*)(g_A1hi + o + 2) = __nv_bfloat162(h[2], h[3]);
    *(__nv_bfloat162*)(g_A1lo + o)     = __nv_bfloat162(l[0], l[1]);
    *(__nv_bfloat162*)(g_A1lo + o + 2) = __nv_bfloat162(l[2], l[3]);
}

// WHICH = 0 -> W1, WHICH = 1 -> W2. Destinations referenced in device code only.
template<int WHICH>
__global__ __launch_bounds__(256)
void conv_split_kernel(const float* __restrict__ src)
{
    constexpr int n4 = (WHICH == 0) ? (HV * EV / 4) : (HV * HV / 4);
    __nv_bfloat16* hi = (WHICH == 0) ? g_W1hi : g_W2hi;
    __nv_bfloat16* lo = (WHICH == 0) ? g_W1lo : g_W2lo;
    int i = blockIdx.x * blockDim.x + threadIdx.x;
    if (i >= n4) return;
    float4 v = ((const float4*)src)[i];
    float vv[4] = {v.x, v.y, v.z, v.w};
    __nv_bfloat16 h[4], l[4];
#pragma unroll
    for (int k = 0; k < 4; k++) {
        h[k] = __float2bfloat16(vv[k]);
        l[k] = __float2bfloat16(vv[k] - __bfloat162float(h[k]));
    }
    size_t o = (size_t)i * 4;
    *(__nv_bfloat162*)(hi + o)     = __nv_bfloat162(h[0], h[1]);
    *(__nv_bfloat162*)(hi + o + 2) = __nv_bfloat162(h[2], h[3]);
    *(__nv_bfloat162*)(lo + o)     = __nv_bfloat162(l[0], l[1]);
    *(__nv_bfloat162*)(lo + o + 2) = __nv_bfloat162(l[2], l[3]);
}

// ============================================================
// Tensor-core GEMM, bf16 2-term split (3 passes), warp mma.sync.
// BK=32 with hi/lo interleaved per 128B row: row r = [hi 64B | lo 64B].
// Stage = A(16KB) + B(16KB) = 32KB; 2 stages = 64KB -> 2 CTAs/SM.
// 256 threads = 8 warps (2M x 4N), warp tile 64x32, block tile 128x128.
// ============================================================
constexpr int STAGE_BYTES = 2 * 16384;     // A tile + B tile
constexpr int SMEM_SZ = 2 * STAGE_BYTES;   // 64 KB

template<int MODE>
__global__ __launch_bounds__(256, 2)
void gemm_t(const float* __restrict__ bias)
{
    constexpr int KDIM = (MODE == 0) ? EV : HV;
    constexpr int NC = KDIM / 32;
    extern __shared__ __align__(1024) char smem[];
    const uint32_t sbase = smem_u32(smem);
    __shared__ float sBias[128];

    const int tid = threadIdx.x;
    const int lane = tid & 31;
    const int wid = tid >> 5;

    int rowA, rowB, bIdx = 0, ti = 0, tj = 0;
    if (MODE == 2) {
        bIdx = blockIdx.y;
        int rem = blockIdx.x;
        while (rem >= (16 - ti)) { rem -= (16 - ti); ti++; }
        tj = ti + rem;
        rowA = bIdx * NV + ti * 128;
        rowB = bIdx * NV + tj * 128;
    } else {
        rowA = blockIdx.x * 128;
        rowB = blockIdx.y * 128;
    }

    // srcs order: Ahi, Alo, Bhi, Blo  (indexed comp*2+half in loader)
    const __nv_bfloat16* srcs[4];
    if (MODE == 0) {
        srcs[0] = g_A1hi + (size_t)rowA * KDIM; srcs[1] = g_A1lo + (size_t)rowA * KDIM;
        srcs[2] = g_W1hi + (size_t)rowB * KDIM; srcs[3] = g_W1lo + (size_t)rowB * KDIM;
    } else if (MODE == 1) {
        srcs[0] = g_hHi + (size_t)rowA * KDIM;  srcs[1] = g_hLo + (size_t)rowA * KDIM;
        srcs[2] = g_W2hi + (size_t)rowB * KDIM; srcs[3] = g_W2lo + (size_t)rowB * KDIM;
    } else {
        srcs[0] = g_nHi + (size_t)rowA * KDIM;  srcs[1] = g_nLo + (size_t)rowA * KDIM;
        srcs[2] = g_nHi + (size_t)rowB * KDIM;  srcs[3] = g_nLo + (size_t)rowB * KDIM;
    }
    if (MODE < 2 && tid < 128) sBias[tid] = bias[blockIdx.y * 128 + tid];

    // ---- stage loader: 2048 x 16B chunks, 8 per thread ----
    auto load_stage = [&](int stage, int c) {
        const uint32_t stBase = sbase + stage * STAGE_BYTES;
        const int k0 = c * 32;
#pragma unroll
        for (int l = 0; l < 8; l++) {
            int s = l * 256 + tid;
            int comp = s >> 10;          // 0 = A, 1 = B
            int t2 = s & 1023;
            int half = t2 >> 9;          // 0 = hi, 1 = lo
            int u = t2 & 511;
            int r = u >> 2;
            int seg = u & 3;
            uint32_t off = (uint32_t)(r * 128 + half * 64 + seg * 16);
            uint32_t dst = stBase + comp * 16384 + (off ^ ((off >> 3) & 0x70));
            const void* gsrc = srcs[comp * 2 + half] + (size_t)r * KDIM + k0 + seg * 8;
            asm volatile("cp.async.cg.shared.global [%0], [%1], 16;"
                         :: "r"(dst), "l"(gsrc));
        }
    };

    // ---- per-thread fragment addressing ----
    const int warpM = (wid >> 2) * 64;
    const int warpN = (wid & 3) * 32;
    const uint32_t xorT = (uint32_t)((lane & 7) << 4);
    uint32_t aRow[4], bRow[2];
#pragma unroll
    for (int mi = 0; mi < 4; mi++)
        aRow[mi] = (uint32_t)((warpM + mi * 16 + (lane & 15)) * 128);
    const int bLocal = (lane & 7) + ((lane >> 4) << 3);
#pragma unroll
    for (int p = 0; p < 2; p++)
        bRow[p] = (uint32_t)((warpN + p * 16 + bLocal) * 128);
    const uint32_t aKsel = (uint32_t)((lane >> 4) << 4);
    const uint32_t bKsel = (uint32_t)(((lane >> 3) & 1) << 4);

    float acc[4][4][4];
#pragma unroll
    for (int mi = 0; mi < 4; mi++)
#pragma unroll
        for (int ni = 0; ni < 4; ni++)
#pragma unroll
            for (int k = 0; k < 4; k++) acc[mi][ni][k] = 0.f;

    auto compute_stage = [&](int stage) {
        const uint32_t stBase = sbase + stage * STAGE_BYTES;
        const uint32_t tA = stBase, tB = stBase + 16384;
#pragma unroll
        for (int ks = 0; ks < 2; ks++) {
            const uint32_t kA = (uint32_t)(ks * 32) + aKsel;
            const uint32_t kB = (uint32_t)(ks * 32) + bKsel;
            uint32_t bh[4][2], bl[4][2];
            {
                uint32_t r0, r1, r2, r3;
                LDSM4(r0, r1, r2, r3, tB + bRow[0] + (kB ^ xorT));
                bh[0][0] = r0; bh[0][1] = r1; bh[1][0] = r2; bh[1][1] = r3;
                LDSM4(r0, r1, r2, r3, tB + bRow[1] + (kB ^ xorT));
                bh[2][0] = r0; bh[2][1] = r1; bh[3][0] = r2; bh[3][1] = r3;
                LDSM4(r0, r1, r2, r3, tB + bRow[0] + ((64 + kB) ^ xorT));
                bl[0][0] = r0; bl[0][1] = r1; bl[1][0] = r2; bl[1][1] = r3;
                LDSM4(r0, r1, r2, r3, tB + bRow[1] + ((64 + kB) ^ xorT));
                bl[2][0] = r0; bl[2][1] = r1; bl[3][0] = r2; bl[3][1] = r3;
            }
            uint32_t a[4][4];
#pragma unroll
            for (int mi = 0; mi < 4; mi++)
                LDSM4(a[mi][0], a[mi][1], a[mi][2], a[mi][3], tA + aRow[mi] + (kA ^ xorT));
            // pass 1: Ahi * Bhi
#pragma unroll
            for (int mi = 0; mi < 4; mi++)
#pragma unroll
                for (int ni = 0; ni < 4; ni++)
                    mma_bf16(acc[mi][ni], a[mi], bh[ni]);
            // pass 2: Ahi * Blo
#pragma unroll
            for (int mi = 0; mi < 4; mi++)
#pragma unroll
                for (int ni = 0; ni < 4; ni++)
                    mma_bf16(acc[mi][ni], a[mi], bl[ni]);
            // pass 3: Alo * Bhi
#pragma unroll
            for (int mi = 0; mi < 4; mi++)
                LDSM4(a[mi][0], a[mi][1], a[mi][2], a[mi][3],
                      tA + aRow[mi] + ((64 + kA) ^ xorT));
#pragma unroll
            for (int mi = 0; mi < 4; mi++)
#pragma unroll
                for (int ni = 0; ni < 4; ni++)
                    mma_bf16(acc[mi][ni], a[mi], bh[ni]);
        }
    };

    // ---- pipelined mainloop ----
    load_stage(0, 0); CP_COMMIT;
    load_stage(1, 1); CP_COMMIT;
    for (int c = 0; c < NC; c++) {
        CP_WAIT1;
        __syncthreads();
        compute_stage(c & 1);
        __syncthreads();
        if (c + 2 < NC) load_stage(c & 1, c + 2);
        CP_COMMIT;
    }

    // ---- epilogue ----
    const int rBase0 = warpM + (lane >> 2);
    const int cBase = warpN + (lane & 3) * 2;

    if (MODE < 2) {
#pragma unroll
        for (int mi = 0; mi < 4; mi++) {
            const int r = rBase0 + mi * 16;
#pragma unroll
            for (int ni = 0; ni < 4; ni++) {
                const int cl = cBase + ni * 8;
                const int gc = blockIdx.y * 128 + cl;
                float v0 = acc[mi][ni][0] + sBias[cl];
                float v1 = acc[mi][ni][1] + sBias[cl + 1];
                float v2 = acc[mi][ni][2] + sBias[cl];
                float v3 = acc[mi][ni][3] + sBias[cl + 1];
                if (MODE == 1) {
                    *(float2*)(g_hidden + (size_t)(rowA + r) * HV + gc) = make_float2(v0, v1);
                    *(float2*)(g_hidden + (size_t)(rowA + r + 8) * HV + gc) = make_float2(v2, v3);
                } else {
                    v0 = fmaxf(v0, 0.f); v1 = fmaxf(v1, 0.f);
                    v2 = fmaxf(v2, 0.f); v3 = fmaxf(v3, 0.f);
                    __nv_bfloat16 h0 = __float2bfloat16(v0), h1 = __float2bfloat16(v1);
                    __nv_bfloat16 h2 = __float2bfloat16(v2), h3 = __float2bfloat16(v3);
                    __nv_bfloat16 l0 = __float2bfloat16(v0 - __bfloat162float(h0));
                    __nv_bfloat16 l1 = __float2bfloat16(v1 - __bfloat162float(h1));
                    __nv_bfloat16 l2 = __float2bfloat16(v2 - __bfloat162float(h2));
                    __nv_bfloat16 l3 = __float2bfloat16(v3 - __bfloat162float(h3));
                    size_t o0 = (size_t)(rowA + r) * HV + gc;
                    size_t o1 = (size_t)(rowA + r + 8) * HV + gc;
                    *(__nv_bfloat162*)(g_hHi + o0) = __nv_bfloat162(h0, h1);
                    *(__nv_bfloat162*)(g_hHi + o1) = __nv_bfloat162(h2, h3);
                    *(__nv_bfloat162*)(g_hLo + o0) = __nv_bfloat162(l0, l1);
                    *(__nv_bfloat162*)(g_hLo + o1) = __nv_bfloat162(l2, l3);
                }
            }
        }
    } else {
        // sim epilogue: softplus, dual reduction via smem atomics
        float* rowAcc = (float*)smem;          // [128]
        float* colAcc = (float*)smem + 128;    // [128]
        if (tid < 256) ((float*)smem)[tid] = 0.f;
        __syncthreads();

        float rowPart[4][2];
        float colPart[4][2];
#pragma unroll
        for (int i = 0; i < 4; i++) {
            rowPart[i][0] = rowPart[i][1] = 0.f;
            colPart[i][0] = colPart[i][1] = 0.f;
        }
#pragma unroll
        for (int mi = 0; mi < 4; mi++)
#pragma unroll
            for (int ni = 0; ni < 4; ni++) {
                float v0 = log1pf(expf(acc[mi][ni][0]));
                float v1 = log1pf(expf(acc[mi][ni][1]));
                float v2 = log1pf(expf(acc[mi][ni][2]));
                float v3 = log1pf(expf(acc[mi][ni][3]));
                rowPart[mi][0] += v0 + v1;
                rowPart[mi][1] += v2 + v3;
                colPart[ni][0] += v0 + v2;
                colPart[ni][1] += v1 + v3;
            }
#pragma unroll
        for (int mi = 0; mi < 4; mi++) {
            atomicAdd(&rowAcc[rBase0 + mi * 16], rowPart[mi][0]);
            atomicAdd(&rowAcc[rBase0 + mi * 16 + 8], rowPart[mi][1]);
        }
#pragma unroll
        for (int ni = 0; ni < 4; ni++) {
            atomicAdd(&colAcc[cBase + ni * 8], colPart[ni][0]);
            atomicAdd(&colAcc[cBase + ni * 8 + 1], colPart[ni][1]);
        }
        __syncthreads();
        if (tid < 128) {
            atomicAdd(&g_c[bIdx * NV + tj * 128 + tid], colAcc[tid]);
            if (ti != tj)
                atomicAdd(&g_c[bIdx * NV + ti * 128 + tid], rowAcc[tid]);
        }
    }
}

// ---------------- normalize -> bf16 hi/lo (also zeroes g_c / g_wit) ----------------
__global__ __launch_bounds__(128)
void norm_kernel()
{
    const int row = blockIdx.x;
    const int t = threadIdx.x;
    const float4 x = ((const float4*)(g_hidden + (size_t)row * HV))[t];
    float ss = x.x * x.x + x.y * x.y + x.z * x.z + x.w * x.w;
#pragma unroll
    for (int o = 16; o; o >>= 1) ss += __shfl_xor_sync(0xffffffffu, ss, o);
    __shared__ float wsum[4];
    if ((t & 31) == 0) wsum[t >> 5] = ss;
    __syncthreads();
    float tot = wsum[0] + wsum[1] + wsum[2] + wsum[3];
    float inv = 1.0f / fmaxf(sqrtf(tot), 1e-12f);
    float vv[4] = {x.x * inv, x.y * inv, x.z * inv, x.w * inv};
    __nv_bfloat16 h[4], l[4];
#pragma unroll
    for (int i = 0; i < 4; i++) {
        h[i] = __float2bfloat16(vv[i]);
        l[i] = __float2bfloat16(vv[i] - __bfloat162float(h[i]));
    }
    size_t o = (size_t)row * HV + t * 4;
    *(__nv_bfloat162*)(g_nHi + o)     = __nv_bfloat162(h[0], h[1]);
    *(__nv_bfloat162*)(g_nHi + o + 2) = __nv_bfloat162(h[2], h[3]);
    *(__nv_bfloat162*)(g_nLo + o)     = __nv_bfloat162(l[0], l[1]);
    *(__nv_bfloat162*)(g_nLo + o + 2) = __nv_bfloat162(l[2], l[3]);
    if (t == 0) {
        g_c[row] = 0.f;
        if (row < BV * HV) g_wit[row] = 0.f;
    }
}

// ---------------- witness: partial sums over m-chunks ----------------
__global__ __launch_bounds__(512)
void witness_kernel()
{
    const int chunk = blockIdx.x;   // 32 chunks of 64 rows
    const int b = blockIdx.y;
    const int h = threadIdx.x;
    __shared__ float cs[64];
    if (threadIdx.x < 64) cs[threadIdx.x] = g_c[b * NV + chunk * 64 + threadIdx.x];
    __syncthreads();
    const float* hp = g_hidden + (size_t)(b * NV + chunk * 64) * HV + h;
    float a = 0.f;
#pragma unroll 8
    for (int m = 0; m < 64; m++)
        a = fmaf(cs[m], hp[(size_t)m * HV], a);
    atomicAdd(&g_wit[b * HV + h], a);
}

// ---------------- output projection ----------------
__global__ __launch_bounds__(512)
void proj_kernel(const float* __restrict__ Wp, const float* __restrict__ bp,
                 float* __restrict__ out)
{
    const int b = blockIdx.x;
    const int g = threadIdx.x;
    __shared__ float w[HV];
    w[g] = g_wit[b * HV + g] * (1.0f / NV);
    __syncthreads();
    float accv = bp[g];
    const float* wp = Wp + (size_t)g * HV;
#pragma unroll 8
    for (int h = 0; h < HV; h++)
        accv = fmaf(w[h], wp[h], accv);
    out[b * HV + g] = accv;
}

extern "C" void kernel_launch(void* const* d_in, const int* in_sizes, int n_in,
                              void* d_out, int out_size)
{
    const int*   tokens = (const int*)d_in[0];
    const float* emb    = (const float*)d_in[1];
    const float* W1     = (const float*)d_in[2];
    const float* b1     = (const float*)d_in[3];
    const float* W2     = (const float*)d_in[4];
    const float* b2     = (const float*)d_in[5];
    const float* Wp     = (const float*)d_in[6];
    const float* bp     = (const float*)d_in[7];
    float* out = (float*)d_out;
    (void)in_sizes; (void)n_in; (void)out_size;

    cudaFuncSetAttribute(gemm_t<0>, cudaFuncAttributeMaxDynamicSharedMemorySize, SMEM_SZ);
    cudaFuncSetAttribute(gemm_t<1>, cudaFuncAttributeMaxDynamicSharedMemorySize, SMEM_SZ);
    cudaFuncSetAttribute(gemm_t<2>, cudaFuncAttributeMaxDynamicSharedMemorySize, SMEM_SZ);

    conv_emb_kernel<<<MROWS / 4, 256>>>(tokens, emb);
    conv_split_kernel<0><<<(HV * EV / 4 + 255) / 256, 256>>>(W1);
    conv_split_kernel<1><<<(HV * HV / 4 + 255) / 256, 256>>>(W2);

    gemm_t<0><<<dim3(MROWS / 128, HV / 128), 256, SMEM_SZ>>>(b1);
    gemm_t<1><<<dim3(MROWS / 128, HV / 128), 256, SMEM_SZ>>>(b2);

    norm_kernel<<<MROWS, 128>>>();

    gemm_t<2><<<dim3(136, BV), 256, SMEM_SZ>>>(nullptr);

    witness_kernel<<<dim3(32, BV), 512>>>();
    proj_kernel<<<BV, 512>>>(Wp, bp, out);
}

// round 7
// speedup vs baseline: 2.6321x; 1.2087x over previous
#include <cuda_runtime.h>
#include <cuda_bf16.h>
#include <cstdint>

#define BV 8
#define NV 2048
#define EV 256
#define HV 512
#define MROWS (BV*NV)   // 16384

// ---------------- scratch (static device globals) ----------------
__device__ __nv_bfloat16 g_A1hi[(size_t)MROWS * EV];
__device__ __nv_bfloat16 g_A1lo[(size_t)MROWS * EV];
__device__ __nv_bfloat16 g_W1hi[HV * EV];
__device__ __nv_bfloat16 g_W1lo[HV * EV];
__device__ __nv_bfloat16 g_W2hi[HV * HV];
__device__ __nv_bfloat16 g_W2lo[HV * HV];
__device__ __nv_bfloat16 g_hHi[(size_t)MROWS * HV];
__device__ __nv_bfloat16 g_hLo[(size_t)MROWS * HV];
__device__ float         g_hidden[(size_t)MROWS * HV];   // fp32, for witness
__device__ __nv_bfloat16 g_nHi[(size_t)MROWS * HV];      // normalized rows, bf16 (single-pass sim)
__device__ float g_c[BV * NV];
__device__ float g_wit[BV * HV];

// ---------------- helpers ----------------
__device__ __forceinline__ uint32_t smem_u32(const void* p) {
    uint32_t a;
    asm("{ .reg .u64 t; cvta.to.shared.u64 t, %1; cvt.u32.u64 %0, t; }" : "=r"(a) : "l"(p));
    return a;
}
__device__ __forceinline__ void mma_bf16(float* c, const uint32_t* a, const uint32_t* b) {
    asm volatile("mma.sync.aligned.m16n8k16.row.col.f32.bf16.bf16.f32 "
                 "{%0,%1,%2,%3}, {%4,%5,%6,%7}, {%8,%9}, {%0,%1,%2,%3};"
                 : "+f"(c[0]), "+f"(c[1]), "+f"(c[2]), "+f"(c[3])
                 : "r"(a[0]), "r"(a[1]), "r"(a[2]), "r"(a[3]),
                   "r"(b[0]), "r"(b[1]));
}
#define LDSM4(r0, r1, r2, r3, addr) \
    asm volatile("ldmatrix.sync.aligned.m8n8.x4.shared.b16 {%0,%1,%2,%3}, [%4];" \
                 : "=r"(r0), "=r"(r1), "=r"(r2), "=r"(r3) : "r"(addr))
#define CP_COMMIT asm volatile("cp.async.commit_group;" ::: "memory")
#define CP_WAIT1  asm volatile("cp.async.wait_group 1;" ::: "memory")

// ---------------- conversion kernels ----------------
__global__ __launch_bounds__(256)
void conv_emb_kernel(const int* __restrict__ tokens, const float* __restrict__ emb)
{
    const int idx = blockIdx.x * 256 + threadIdx.x;   // one float4 per thread
    const int row = idx >> 6;                         // 64 quads per row
    const int t = idx & 63;
    const int tok = tokens[row];
    float4 v = *(const float4*)(emb + (size_t)tok * EV + t * 4);
    float vv[4] = {v.x, v.y, v.z, v.w};
    __nv_bfloat16 h[4], l[4];
#pragma unroll
    for (int i = 0; i < 4; i++) {
        h[i] = __float2bfloat16(vv[i]);
        l[i] = __float2bfloat16(vv[i] - __bfloat162float(h[i]));
    }
    size_t o = (size_t)row * EV + t * 4;
    *(__nv_bfloat162*)(g_A1hi + o)     = __nv_bfloat162(h[0], h[1]);
    *(__nv_bfloat162*)(g_A1hi + o + 2) = __nv_bfloat162(h[2], h[3]);
    *(__nv_bfloat162*)(g_A1lo + o)     = __nv_bfloat162(l[0], l[1]);
    *(__nv_bfloat162*)(g_A1lo + o + 2) = __nv_bfloat162(l[2], l[3]);
}

// WHICH = 0 -> W1, WHICH = 1 -> W2. Destinations referenced in device code only.
template<int WHICH>
__global__ __launch_bounds__(256)
void conv_split_kernel(const float* __restrict__ src)
{
    constexpr int n4 = (WHICH == 0) ? (HV * EV / 4) : (HV * HV / 4);
    __nv_bfloat16* hi = (WHICH == 0) ? g_W1hi : g_W2hi;
    __nv_bfloat16* lo = (WHICH == 0) ? g_W1lo : g_W2lo;
    int i = blockIdx.x * blockDim.x + threadIdx.x;
    if (i >= n4) return;
    float4 v = ((const float4*)src)[i];
    float vv[4] = {v.x, v.y, v.z, v.w};
    __nv_bfloat16 h[4], l[4];
#pragma unroll
    for (int k = 0; k < 4; k++) {
        h[k] = __float2bfloat16(vv[k]);
        l[k] = __float2bfloat16(vv[k] - __bfloat162float(h[k]));
    }
    size_t o = (size_t)i * 4;
    *(__nv_bfloat162*)(hi + o)     = __nv_bfloat162(h[0], h[1]);
    *(__nv_bfloat162*)(hi + o + 2) = __nv_bfloat162(h[2], h[3]);
    *(__nv_bfloat162*)(lo + o)     = __nv_bfloat162(l[0], l[1]);
    *(__nv_bfloat162*)(lo + o + 2) = __nv_bfloat162(l[2], l[3]);
}

// ============================================================
// Tensor-core GEMM via warp mma.sync.
// MODE 0/1: bf16 2-term split (3 passes). Rows hold [hi 64B | lo 64B] of k32.
// MODE 2  : single-pass bf16 (error analysis: sim errors average out in c).
//           Rows hold k64 of pure hi data -> half the traffic.
// Stage = A(16KB)+B(16KB) = 32KB; 2 stages = 64KB -> 2 CTAs/SM.
// 256 threads = 8 warps (2M x 4N), warp tile 64x32, block tile 128x128.
// ============================================================
constexpr int STAGE_BYTES = 2 * 16384;
constexpr int SMEM_SZ = 2 * STAGE_BYTES;   // 64 KB

template<int MODE>
__global__ __launch_bounds__(256, 2)
void gemm_t(const float* __restrict__ bias)
{
    constexpr int KDIM = (MODE == 0) ? EV : HV;
    constexpr int BKC = (MODE == 2) ? 64 : 32;   // k elems consumed per stage
    constexpr int NC = KDIM / BKC;               // 8 / 16 / 8
    extern __shared__ __align__(1024) char smem[];
    const uint32_t sbase = smem_u32(smem);
    __shared__ float sBias[128];

    const int tid = threadIdx.x;
    const int lane = tid & 31;
    const int wid = tid >> 5;

    int rowA, rowB, bIdx = 0, ti = 0, tj = 0;
    if (MODE == 2) {
        bIdx = blockIdx.y;
        int rem = blockIdx.x;
        while (rem >= (16 - ti)) { rem -= (16 - ti); ti++; }
        tj = ti + rem;
        rowA = bIdx * NV + ti * 128;
        rowB = bIdx * NV + tj * 128;
    } else {
        rowA = blockIdx.x * 128;
        rowB = blockIdx.y * 128;
    }

    // srcs order: Ahi, Alo, Bhi, Blo (MODE 2 uses Ahi/Bhi slots only)
    const __nv_bfloat16* srcs[4];
    if (MODE == 0) {
        srcs[0] = g_A1hi + (size_t)rowA * KDIM; srcs[1] = g_A1lo + (size_t)rowA * KDIM;
        srcs[2] = g_W1hi + (size_t)rowB * KDIM; srcs[3] = g_W1lo + (size_t)rowB * KDIM;
    } else if (MODE == 1) {
        srcs[0] = g_hHi + (size_t)rowA * KDIM;  srcs[1] = g_hLo + (size_t)rowA * KDIM;
        srcs[2] = g_W2hi + (size_t)rowB * KDIM; srcs[3] = g_W2lo + (size_t)rowB * KDIM;
    } else {
        srcs[0] = g_nHi + (size_t)rowA * KDIM;  srcs[1] = srcs[0];
        srcs[2] = g_nHi + (size_t)rowB * KDIM;  srcs[3] = srcs[2];
    }
    if (MODE < 2 && tid < 128) sBias[tid] = bias[blockIdx.y * 128 + tid];

    // ---- stage loader: 2048 x 16B chunks, 8 per thread ----
    auto load_stage = [&](int stage, int c) {
        const uint32_t stBase = sbase + stage * STAGE_BYTES;
        const int k0 = c * BKC;
#pragma unroll
        for (int l = 0; l < 8; l++) {
            int s = l * 256 + tid;
            int comp = s >> 10;          // 0 = A, 1 = B
            int u = s & 1023;
            const __nv_bfloat16* gsrc;
            int r, seg;
            if (MODE == 2) {
                r = u >> 3; seg = u & 7;                 // 8 x 16B segs of pure data
                gsrc = srcs[comp * 2] + (size_t)r * KDIM + k0 + seg * 8;
            } else {
                int half = u >> 9; int u2 = u & 511;
                r = u2 >> 2; int sg = u2 & 3;
                gsrc = srcs[comp * 2 + half] + (size_t)r * KDIM + k0 + sg * 8;
                seg = half * 4 + sg;                      // [hi 64B | lo 64B]
            }
            uint32_t off = (uint32_t)(r * 128 + seg * 16);
            uint32_t dst = stBase + comp * 16384 + (off ^ ((off >> 3) & 0x70));
            asm volatile("cp.async.cg.shared.global [%0], [%1], 16;"
                         :: "r"(dst), "l"(gsrc));
        }
    };

    // ---- per-thread fragment addressing ----
    const int warpM = (wid >> 2) * 64;
    const int warpN = (wid & 3) * 32;
    const uint32_t xorT = (uint32_t)((lane & 7) << 4);
    uint32_t aRow[4], bRow[2];
#pragma unroll
    for (int mi = 0; mi < 4; mi++)
        aRow[mi] = (uint32_t)((warpM + mi * 16 + (lane & 15)) * 128);
    const int bLocal = (lane & 7) + ((lane >> 4) << 3);
#pragma unroll
    for (int p = 0; p < 2; p++)
        bRow[p] = (uint32_t)((warpN + p * 16 + bLocal) * 128);
    const uint32_t aKsel = (uint32_t)((lane >> 4) << 4);
    const uint32_t bKsel = (uint32_t)(((lane >> 3) & 1) << 4);

    float acc[4][4][4];
#pragma unroll
    for (int mi = 0; mi < 4; mi++)
#pragma unroll
        for (int ni = 0; ni < 4; ni++)
#pragma unroll
            for (int k = 0; k < 4; k++) acc[mi][ni][k] = 0.f;

    auto compute_stage = [&](int stage) {
        const uint32_t stBase = sbase + stage * STAGE_BYTES;
        const uint32_t tA = stBase, tB = stBase + 16384;
        if (MODE == 2) {
            // single pass, 4 k16 steps per stage
#pragma unroll
            for (int ks = 0; ks < 4; ks++) {
                const uint32_t kk = (uint32_t)(ks * 32);
                uint32_t bh[4][2];
                {
                    uint32_t r0, r1, r2, r3;
                    LDSM4(r0, r1, r2, r3, tB + bRow[0] + ((kk + bKsel) ^ xorT));
                    bh[0][0] = r0; bh[0][1] = r1; bh[1][0] = r2; bh[1][1] = r3;
                    LDSM4(r0, r1, r2, r3, tB + bRow[1] + ((kk + bKsel) ^ xorT));
                    bh[2][0] = r0; bh[2][1] = r1; bh[3][0] = r2; bh[3][1] = r3;
                }
                uint32_t a[4][4];
#pragma unroll
                for (int mi = 0; mi < 4; mi++)
                    LDSM4(a[mi][0], a[mi][1], a[mi][2], a[mi][3],
                          tA + aRow[mi] + ((kk + aKsel) ^ xorT));
#pragma unroll
                for (int mi = 0; mi < 4; mi++)
#pragma unroll
                    for (int ni = 0; ni < 4; ni++)
                        mma_bf16(acc[mi][ni], a[mi], bh[ni]);
            }
        } else {
            // 3-pass split, 2 k16 steps per stage
#pragma unroll
            for (int ks = 0; ks < 2; ks++) {
                const uint32_t kA = (uint32_t)(ks * 32) + aKsel;
                const uint32_t kB = (uint32_t)(ks * 32) + bKsel;
                uint32_t bh[4][2], bl[4][2];
                {
                    uint32_t r0, r1, r2, r3;
                    LDSM4(r0, r1, r2, r3, tB + bRow[0] + (kB ^ xorT));
                    bh[0][0] = r0; bh[0][1] = r1; bh[1][0] = r2; bh[1][1] = r3;
                    LDSM4(r0, r1, r2, r3, tB + bRow[1] + (kB ^ xorT));
                    bh[2][0] = r0; bh[2][1] = r1; bh[3][0] = r2; bh[3][1] = r3;
                    LDSM4(r0, r1, r2, r3, tB + bRow[0] + ((64 + kB) ^ xorT));
                    bl[0][0] = r0; bl[0][1] = r1; bl[1][0] = r2; bl[1][1] = r3;
                    LDSM4(r0, r1, r2, r3, tB + bRow[1] + ((64 + kB) ^ xorT));
                    bl[2][0] = r0; bl[2][1] = r1; bl[3][0] = r2; bl[3][1] = r3;
                }
                uint32_t a[4][4];
#pragma unroll
                for (int mi = 0; mi < 4; mi++)
                    LDSM4(a[mi][0], a[mi][1], a[mi][2], a[mi][3], tA + aRow[mi] + (kA ^ xorT));
#pragma unroll
                for (int mi = 0; mi < 4; mi++)
#pragma unroll
                    for (int ni = 0; ni < 4; ni++)
                        mma_bf16(acc[mi][ni], a[mi], bh[ni]);
#pragma unroll
                for (int mi = 0; mi < 4; mi++)
#pragma unroll
                    for (int ni = 0; ni < 4; ni++)
                        mma_bf16(acc[mi][ni], a[mi], bl[ni]);
#pragma unroll
                for (int mi = 0; mi < 4; mi++)
                    LDSM4(a[mi][0], a[mi][1], a[mi][2], a[mi][3],
                          tA + aRow[mi] + ((64 + kA) ^ xorT));
#pragma unroll
                for (int mi = 0; mi < 4; mi++)
#pragma unroll
                    for (int ni = 0; ni < 4; ni++)
                        mma_bf16(acc[mi][ni], a[mi], bh[ni]);
            }
        }
    };

    // ---- pipelined mainloop ----
    load_stage(0, 0); CP_COMMIT;
    load_stage(1, 1); CP_COMMIT;
    for (int c = 0; c < NC; c++) {
        CP_WAIT1;
        __syncthreads();
        compute_stage(c & 1);
        __syncthreads();
        if (c + 2 < NC) load_stage(c & 1, c + 2);
        CP_COMMIT;
    }

    // ---- epilogue ----
    const int rBase0 = warpM + (lane >> 2);
    const int cBase = warpN + (lane & 3) * 2;

    if (MODE < 2) {
#pragma unroll
        for (int mi = 0; mi < 4; mi++) {
            const int r = rBase0 + mi * 16;
#pragma unroll
            for (int ni = 0; ni < 4; ni++) {
                const int cl = cBase + ni * 8;
                const int gc = blockIdx.y * 128 + cl;
                float v0 = acc[mi][ni][0] + sBias[cl];
                float v1 = acc[mi][ni][1] + sBias[cl + 1];
                float v2 = acc[mi][ni][2] + sBias[cl];
                float v3 = acc[mi][ni][3] + sBias[cl + 1];
                if (MODE == 1) {
                    *(float2*)(g_hidden + (size_t)(rowA + r) * HV + gc) = make_float2(v0, v1);
                    *(float2*)(g_hidden + (size_t)(rowA + r + 8) * HV + gc) = make_float2(v2, v3);
                } else {
                    v0 = fmaxf(v0, 0.f); v1 = fmaxf(v1, 0.f);
                    v2 = fmaxf(v2, 0.f); v3 = fmaxf(v3, 0.f);
                    __nv_bfloat16 h0 = __float2bfloat16(v0), h1 = __float2bfloat16(v1);
                    __nv_bfloat16 h2 = __float2bfloat16(v2), h3 = __float2bfloat16(v3);
                    __nv_bfloat16 l0 = __float2bfloat16(v0 - __bfloat162float(h0));
                    __nv_bfloat16 l1 = __float2bfloat16(v1 - __bfloat162float(h1));
                    __nv_bfloat16 l2 = __float2bfloat16(v2 - __bfloat162float(h2));
                    __nv_bfloat16 l3 = __float2bfloat16(v3 - __bfloat162float(h3));
                    size_t o0 = (size_t)(rowA + r) * HV + gc;
                    size_t o1 = (size_t)(rowA + r + 8) * HV + gc;
                    *(__nv_bfloat162*)(g_hHi + o0) = __nv_bfloat162(h0, h1);
                    *(__nv_bfloat162*)(g_hHi + o1) = __nv_bfloat162(h2, h3);
                    *(__nv_bfloat162*)(g_hLo + o0) = __nv_bfloat162(l0, l1);
                    *(__nv_bfloat162*)(g_hLo + o1) = __nv_bfloat162(l2, l3);
                }
            }
        }
    } else {
        // sim epilogue: softplus, dual reduction via smem atomics
        float* rowAcc = (float*)smem;          // [128]
        float* colAcc = (float*)smem + 128;    // [128]
        if (tid < 256) ((float*)smem)[tid] = 0.f;
        __syncthreads();

        float rowPart[4][2];
        float colPart[4][2];
#pragma unroll
        for (int i = 0; i < 4; i++) {
            rowPart[i][0] = rowPart[i][1] = 0.f;
            colPart[i][0] = colPart[i][1] = 0.f;
        }
#pragma unroll
        for (int mi = 0; mi < 4; mi++)
#pragma unroll
            for (int ni = 0; ni < 4; ni++) {
                float v0 = log1pf(expf(acc[mi][ni][0]));
                float v1 = log1pf(expf(acc[mi][ni][1]));
                float v2 = log1pf(expf(acc[mi][ni][2]));
                float v3 = log1pf(expf(acc[mi][ni][3]));
                rowPart[mi][0] += v0 + v1;
                rowPart[mi][1] += v2 + v3;
                colPart[ni][0] += v0 + v2;
                colPart[ni][1] += v1 + v3;
            }
#pragma unroll
        for (int mi = 0; mi < 4; mi++) {
            atomicAdd(&rowAcc[rBase0 + mi * 16], rowPart[mi][0]);
            atomicAdd(&rowAcc[rBase0 + mi * 16 + 8], rowPart[mi][1]);
        }
#pragma unroll
        for (int ni = 0; ni < 4; ni++) {
            atomicAdd(&colAcc[cBase + ni * 8], colPart[ni][0]);
            atomicAdd(&colAcc[cBase + ni * 8 + 1], colPart[ni][1]);
        }
        __syncthreads();
        if (tid < 128) {
            atomicAdd(&g_c[bIdx * NV + tj * 128 + tid], colAcc[tid]);
            if (ti != tj)
                atomicAdd(&g_c[bIdx * NV + ti * 128 + tid], rowAcc[tid]);
        }
    }
}

// ---------------- normalize -> bf16 (also zeroes g_c / g_wit) ----------------
__global__ __launch_bounds__(128)
void norm_kernel()
{
    const int row = blockIdx.x;
    const int t = threadIdx.x;
    const float4 x = ((const float4*)(g_hidden + (size_t)row * HV))[t];
    float ss = x.x * x.x + x.y * x.y + x.z * x.z + x.w * x.w;
#pragma unroll
    for (int o = 16; o; o >>= 1) ss += __shfl_xor_sync(0xffffffffu, ss, o);
    __shared__ float wsum[4];
    if ((t & 31) == 0) wsum[t >> 5] = ss;
    __syncthreads();
    float tot = wsum[0] + wsum[1] + wsum[2] + wsum[3];
    float inv = 1.0f / fmaxf(sqrtf(tot), 1e-12f);
    __nv_bfloat16 h0 = __float2bfloat16(x.x * inv);
    __nv_bfloat16 h1 = __float2bfloat16(x.y * inv);
    __nv_bfloat16 h2 = __float2bfloat16(x.z * inv);
    __nv_bfloat16 h3 = __float2bfloat16(x.w * inv);
    size_t o = (size_t)row * HV + t * 4;
    *(__nv_bfloat162*)(g_nHi + o)     = __nv_bfloat162(h0, h1);
    *(__nv_bfloat162*)(g_nHi + o + 2) = __nv_bfloat162(h2, h3);
    if (t == 0) {
        g_c[row] = 0.f;
        if (row < BV * HV) g_wit[row] = 0.f;
    }
}

// ---------------- witness: partial sums over m-chunks ----------------
__global__ __launch_bounds__(512)
void witness_kernel()
{
    const int chunk = blockIdx.x;   // 32 chunks of 64 rows
    const int b = blockIdx.y;
    const int h = threadIdx.x;
    __shared__ float cs[64];
    if (threadIdx.x < 64) cs[threadIdx.x] = g_c[b * NV + chunk * 64 + threadIdx.x];
    __syncthreads();
    const float* hp = g_hidden + (size_t)(b * NV + chunk * 64) * HV + h;
    float a = 0.f;
#pragma unroll 8
    for (int m = 0; m < 64; m++)
        a = fmaf(cs[m], hp[(size_t)m * HV], a);
    atomicAdd(&g_wit[b * HV + h], a);
}

// ---------------- output projection ----------------
__global__ __launch_bounds__(512)
void proj_kernel(const float* __restrict__ Wp, const float* __restrict__ bp,
                 float* __restrict__ out)
{
    const int b = blockIdx.x;
    const int g = threadIdx.x;
    __shared__ float w[HV];
    w[g] = g_wit[b * HV + g] * (1.0f / NV);
    __syncthreads();
    float accv = bp[g];
    const float* wp = Wp + (size_t)g * HV;
#pragma unroll 8
    for (int h = 0; h < HV; h++)
        accv = fmaf(w[h], wp[h], accv);
    out[b * HV + g] = accv;
}

extern "C" void kernel_launch(void* const* d_in, const int* in_sizes, int n_in,
                              void* d_out, int out_size)
{
    const int*   tokens = (const int*)d_in[0];
    const float* emb    = (const float*)d_in[1];
    const float* W1     = (const float*)d_in[2];
    const float* b1     = (const float*)d_in[3];
    const float* W2     = (const float*)d_in[4];
    const float* b2     = (const float*)d_in[5];
    const float* Wp     = (const float*)d_in[6];
    const float* bp     = (const float*)d_in[7];
    float* out = (float*)d_out;
    (void)in_sizes; (void)n_in; (void)out_size;

    cudaFuncSetAttribute(gemm_t<0>, cudaFuncAttributeMaxDynamicSharedMemorySize, SMEM_SZ);
    cudaFuncSetAttribute(gemm_t<1>, cudaFuncAttributeMaxDynamicSharedMemorySize, SMEM_SZ);
    cudaFuncSetAttribute(gemm_t<2>, cudaFuncAttributeMaxDynamicSharedMemorySize, SMEM_SZ);

    conv_emb_kernel<<<MROWS / 4, 256>>>(tokens, emb);
    conv_split_kernel<0><<<(HV * EV / 4 + 255) / 256, 256>>>(W1);
    conv_split_kernel<1><<<(HV * HV / 4 + 255) / 256, 256>>>(W2);

    gemm_t<0><<<dim3(MROWS / 128, HV / 128), 256, SMEM_SZ>>>(b1);
    gemm_t<1><<<dim3(MROWS / 128, HV / 128), 256, SMEM_SZ>>>(b2);

    norm_kernel<<<MROWS, 128>>>();

    gemm_t<2><<<dim3(136, BV), 256, SMEM_SZ>>>(nullptr);

    witness_kernel<<<dim3(32, BV), 512>>>();
    proj_kernel<<<BV, 512>>>(Wp, bp, out);
}

// round 8
// speedup vs baseline: 3.2140x; 1.2211x over previous
#include <cuda_runtime.h>
#include <cuda_fp16.h>
#include <cstdint>

#define BV 8
#define NV 2048
#define EV 256
#define HV 512
#define MROWS (BV*NV)   // 16384

// ---------------- scratch (static device globals) ----------------
__device__ __half g_A16[(size_t)MROWS * EV];     // fp16 gathered embeddings
__device__ __half g_W1h[HV * EV];
__device__ __half g_W2h[HV * HV];
__device__ __half g_h16[(size_t)MROWS * HV];     // relu(emb@W1+b1), fp16
__device__ float  g_hidden[(size_t)MROWS * HV];  // fp32, for witness
__device__ __half g_n16[(size_t)MROWS * HV];     // normalized rows, fp16
__device__ float g_c[BV * NV];
__device__ float g_wit[BV * HV];

// ---------------- helpers ----------------
__device__ __forceinline__ uint32_t smem_u32(const void* p) {
    uint32_t a;
    asm("{ .reg .u64 t; cvta.to.shared.u64 t, %1; cvt.u32.u64 %0, t; }" : "=r"(a) : "l"(p));
    return a;
}
__device__ __forceinline__ void mma_f16(float* c, const uint32_t* a, const uint32_t* b) {
    asm volatile("mma.sync.aligned.m16n8k16.row.col.f32.f16.f16.f32 "
                 "{%0,%1,%2,%3}, {%4,%5,%6,%7}, {%8,%9}, {%0,%1,%2,%3};"
                 : "+f"(c[0]), "+f"(c[1]), "+f"(c[2]), "+f"(c[3])
                 : "r"(a[0]), "r"(a[1]), "r"(a[2]), "r"(a[3]),
                   "r"(b[0]), "r"(b[1]));
}
#define LDSM4(r0, r1, r2, r3, addr) \
    asm volatile("ldmatrix.sync.aligned.m8n8.x4.shared.b16 {%0,%1,%2,%3}, [%4];" \
                 : "=r"(r0), "=r"(r1), "=r"(r2), "=r"(r3) : "r"(addr))
#define CP_COMMIT asm volatile("cp.async.commit_group;" ::: "memory")
#define CP_WAIT1  asm volatile("cp.async.wait_group 1;" ::: "memory")

// ---------------- conversion kernels ----------------
__global__ __launch_bounds__(256)
void conv_emb_kernel(const int* __restrict__ tokens, const float* __restrict__ emb)
{
    const int idx = blockIdx.x * 256 + threadIdx.x;   // one float4 per thread
    const int row = idx >> 6;                         // 64 quads per row
    const int t = idx & 63;
    const int tok = tokens[row];
    float4 v = *(const float4*)(emb + (size_t)tok * EV + t * 4);
    size_t o = (size_t)row * EV + t * 4;
    *(__half2*)(g_A16 + o)     = __floats2half2_rn(v.x, v.y);
    *(__half2*)(g_A16 + o + 2) = __floats2half2_rn(v.z, v.w);
}

// WHICH = 0 -> W1, WHICH = 1 -> W2. Destinations referenced in device code only.
template<int WHICH>
__global__ __launch_bounds__(256)
void conv_w_kernel(const float* __restrict__ src)
{
    constexpr int n4 = (WHICH == 0) ? (HV * EV / 4) : (HV * HV / 4);
    __half* dst = (WHICH == 0) ? g_W1h : g_W2h;
    int i = blockIdx.x * blockDim.x + threadIdx.x;
    if (i >= n4) return;
    float4 v = ((const float4*)src)[i];
    size_t o = (size_t)i * 4;
    *(__half2*)(dst + o)     = __floats2half2_rn(v.x, v.y);
    *(__half2*)(dst + o + 2) = __floats2half2_rn(v.z, v.w);
}

// ============================================================
// Tensor-core GEMM via warp mma.sync, single-pass fp16, fp32 accum.
// MODE 0: relu(A16 @ W1^T + b1) -> g_h16          (K=256)
// MODE 1: h16 @ W2^T + b2       -> g_hidden fp32  (K=512)
// MODE 2: triangular sim tiles  -> softplus -> g_c (K=512)
// Rows of 128B hold k64 fp16. Stage = A(16KB)+B(16KB) = 32KB; 2 stages -> 2 CTAs/SM.
// 256 threads = 8 warps (2M x 4N), warp tile 64x32, block tile 128x128.
// ============================================================
constexpr int STAGE_BYTES = 2 * 16384;
constexpr int SMEM_SZ = 2 * STAGE_BYTES;   // 64 KB

template<int MODE>
__global__ __launch_bounds__(256, 2)
void gemm_t(const float* __restrict__ bias)
{
    constexpr int KDIM = (MODE == 0) ? EV : HV;
    constexpr int NC = KDIM / 64;
    extern __shared__ __align__(1024) char smem[];
    const uint32_t sbase = smem_u32(smem);
    __shared__ float sBias[128];

    const int tid = threadIdx.x;
    const int lane = tid & 31;
    const int wid = tid >> 5;

    int rowA, rowB, bIdx = 0, ti = 0, tj = 0;
    if (MODE == 2) {
        bIdx = blockIdx.y;
        int rem = blockIdx.x;
        while (rem >= (16 - ti)) { rem -= (16 - ti); ti++; }
        tj = ti + rem;
        rowA = bIdx * NV + ti * 128;
        rowB = bIdx * NV + tj * 128;
    } else {
        rowA = blockIdx.x * 128;
        rowB = blockIdx.y * 128;
    }

    const __half* srcA;
    const __half* srcB;
    if (MODE == 0) {
        srcA = g_A16 + (size_t)rowA * KDIM;
        srcB = g_W1h + (size_t)rowB * KDIM;
    } else if (MODE == 1) {
        srcA = g_h16 + (size_t)rowA * KDIM;
        srcB = g_W2h + (size_t)rowB * KDIM;
    } else {
        srcA = g_n16 + (size_t)rowA * KDIM;
        srcB = g_n16 + (size_t)rowB * KDIM;
    }
    if (MODE < 2 && tid < 128) sBias[tid] = bias[blockIdx.y * 128 + tid];

    // ---- stage loader: 2048 x 16B chunks, 8 per thread ----
    auto load_stage = [&](int stage, int c) {
        const uint32_t stBase = sbase + stage * STAGE_BYTES;
        const int k0 = c * 64;
#pragma unroll
        for (int l = 0; l < 8; l++) {
            int s = l * 256 + tid;
            int comp = s >> 10;          // 0 = A, 1 = B
            int u = s & 1023;
            int r = u >> 3, seg = u & 7;
            const __half* gsrc = (comp ? srcB : srcA) + (size_t)r * KDIM + k0 + seg * 8;
            uint32_t off = (uint32_t)(r * 128 + seg * 16);
            uint32_t dst = stBase + comp * 16384 + (off ^ ((off >> 3) & 0x70));
            asm volatile("cp.async.cg.shared.global [%0], [%1], 16;"
                         :: "r"(dst), "l"(gsrc));
        }
    };

    // ---- per-thread fragment addressing ----
    const int warpM = (wid >> 2) * 64;
    const int warpN = (wid & 3) * 32;
    const uint32_t xorT = (uint32_t)((lane & 7) << 4);
    uint32_t aRow[4], bRow[2];
#pragma unroll
    for (int mi = 0; mi < 4; mi++)
        aRow[mi] = (uint32_t)((warpM + mi * 16 + (lane & 15)) * 128);
    const int bLocal = (lane & 7) + ((lane >> 4) << 3);
#pragma unroll
    for (int p = 0; p < 2; p++)
        bRow[p] = (uint32_t)((warpN + p * 16 + bLocal) * 128);
    const uint32_t aKsel = (uint32_t)((lane >> 4) << 4);
    const uint32_t bKsel = (uint32_t)(((lane >> 3) & 1) << 4);

    float acc[4][4][4];
#pragma unroll
    for (int mi = 0; mi < 4; mi++)
#pragma unroll
        for (int ni = 0; ni < 4; ni++)
#pragma unroll
            for (int k = 0; k < 4; k++) acc[mi][ni][k] = 0.f;

    auto compute_stage = [&](int stage) {
        const uint32_t stBase = sbase + stage * STAGE_BYTES;
        const uint32_t tA = stBase, tB = stBase + 16384;
#pragma unroll
        for (int ks = 0; ks < 4; ks++) {
            const uint32_t kk = (uint32_t)(ks * 32);
            uint32_t bh[4][2];
            {
                uint32_t r0, r1, r2, r3;
                LDSM4(r0, r1, r2, r3, tB + bRow[0] + ((kk + bKsel) ^ xorT));
                bh[0][0] = r0; bh[0][1] = r1; bh[1][0] = r2; bh[1][1] = r3;
                LDSM4(r0, r1, r2, r3, tB + bRow[1] + ((kk + bKsel) ^ xorT));
                bh[2][0] = r0; bh[2][1] = r1; bh[3][0] = r2; bh[3][1] = r3;
            }
            uint32_t a[4][4];
#pragma unroll
            for (int mi = 0; mi < 4; mi++)
                LDSM4(a[mi][0], a[mi][1], a[mi][2], a[mi][3],
                      tA + aRow[mi] + ((kk + aKsel) ^ xorT));
#pragma unroll
            for (int mi = 0; mi < 4; mi++)
#pragma unroll
                for (int ni = 0; ni < 4; ni++)
                    mma_f16(acc[mi][ni], a[mi], bh[ni]);
        }
    };

    // ---- pipelined mainloop ----
    load_stage(0, 0); CP_COMMIT;
    load_stage(1, 1); CP_COMMIT;
    for (int c = 0; c < NC; c++) {
        CP_WAIT1;
        __syncthreads();
        compute_stage(c & 1);
        __syncthreads();
        if (c + 2 < NC) load_stage(c & 1, c + 2);
        CP_COMMIT;
    }

    // ---- epilogue ----
    const int rBase0 = warpM + (lane >> 2);
    const int cBase = warpN + (lane & 3) * 2;

    if (MODE < 2) {
#pragma unroll
        for (int mi = 0; mi < 4; mi++) {
            const int r = rBase0 + mi * 16;
#pragma unroll
            for (int ni = 0; ni < 4; ni++) {
                const int cl = cBase + ni * 8;
                const int gc = blockIdx.y * 128 + cl;
                float v0 = acc[mi][ni][0] + sBias[cl];
                float v1 = acc[mi][ni][1] + sBias[cl + 1];
                float v2 = acc[mi][ni][2] + sBias[cl];
                float v3 = acc[mi][ni][3] + sBias[cl + 1];
                if (MODE == 1) {
                    *(float2*)(g_hidden + (size_t)(rowA + r) * HV + gc) = make_float2(v0, v1);
                    *(float2*)(g_hidden + (size_t)(rowA + r + 8) * HV + gc) = make_float2(v2, v3);
                } else {
                    v0 = fmaxf(v0, 0.f); v1 = fmaxf(v1, 0.f);
                    v2 = fmaxf(v2, 0.f); v3 = fmaxf(v3, 0.f);
                    size_t o0 = (size_t)(rowA + r) * HV + gc;
                    size_t o1 = (size_t)(rowA + r + 8) * HV + gc;
                    *(__half2*)(g_h16 + o0) = __floats2half2_rn(v0, v1);
                    *(__half2*)(g_h16 + o1) = __floats2half2_rn(v2, v3);
                }
            }
        }
    } else {
        // sim epilogue: softplus, dual reduction via smem atomics
        float* rowAcc = (float*)smem;          // [128]
        float* colAcc = (float*)smem + 128;    // [128]
        if (tid < 256) ((float*)smem)[tid] = 0.f;
        __syncthreads();

        float rowPart[4][2];
        float colPart[4][2];
#pragma unroll
        for (int i = 0; i < 4; i++) {
            rowPart[i][0] = rowPart[i][1] = 0.f;
            colPart[i][0] = colPart[i][1] = 0.f;
        }
#pragma unroll
        for (int mi = 0; mi < 4; mi++)
#pragma unroll
            for (int ni = 0; ni < 4; ni++) {
                float v0 = log1pf(expf(acc[mi][ni][0]));
                float v1 = log1pf(expf(acc[mi][ni][1]));
                float v2 = log1pf(expf(acc[mi][ni][2]));
                float v3 = log1pf(expf(acc[mi][ni][3]));
                rowPart[mi][0] += v0 + v1;
                rowPart[mi][1] += v2 + v3;
                colPart[ni][0] += v0 + v2;
                colPart[ni][1] += v1 + v3;
            }
#pragma unroll
        for (int mi = 0; mi < 4; mi++) {
            atomicAdd(&rowAcc[rBase0 + mi * 16], rowPart[mi][0]);
            atomicAdd(&rowAcc[rBase0 + mi * 16 + 8], rowPart[mi][1]);
        }
#pragma unroll
        for (int ni = 0; ni < 4; ni++) {
            atomicAdd(&colAcc[cBase + ni * 8], colPart[ni][0]);
            atomicAdd(&colAcc[cBase + ni * 8 + 1], colPart[ni][1]);
        }
        __syncthreads();
        if (tid < 128) {
            atomicAdd(&g_c[bIdx * NV + tj * 128 + tid], colAcc[tid]);
            if (ti != tj)
                atomicAdd(&g_c[bIdx * NV + ti * 128 + tid], rowAcc[tid]);
        }
    }
}

// ---------------- normalize -> fp16 (also zeroes g_c / g_wit) ----------------
__global__ __launch_bounds__(128)
void norm_kernel()
{
    const int row = blockIdx.x;
    const int t = threadIdx.x;
    const float4 x = ((const float4*)(g_hidden + (size_t)row * HV))[t];
    float ss = x.x * x.x + x.y * x.y + x.z * x.z + x.w * x.w;
#pragma unroll
    for (int o = 16; o; o >>= 1) ss += __shfl_xor_sync(0xffffffffu, ss, o);
    __shared__ float wsum[4];
    if ((t & 31) == 0) wsum[t >> 5] = ss;
    __syncthreads();
    float tot = wsum[0] + wsum[1] + wsum[2] + wsum[3];
    float inv = 1.0f / fmaxf(sqrtf(tot), 1e-12f);
    size_t o = (size_t)row * HV + t * 4;
    *(__half2*)(g_n16 + o)     = __floats2half2_rn(x.x * inv, x.y * inv);
    *(__half2*)(g_n16 + o + 2) = __floats2half2_rn(x.z * inv, x.w * inv);
    if (t == 0) {
        g_c[row] = 0.f;
        if (row < BV * HV) g_wit[row] = 0.f;
    }
}

// ---------------- witness: partial sums over m-chunks ----------------
__global__ __launch_bounds__(512)
void witness_kernel()
{
    const int chunk = blockIdx.x;   // 32 chunks of 64 rows
    const int b = blockIdx.y;
    const int h = threadIdx.x;
    __shared__ float cs[64];
    if (threadIdx.x < 64) cs[threadIdx.x] = g_c[b * NV + chunk * 64 + threadIdx.x];
    __syncthreads();
    const float* hp = g_hidden + (size_t)(b * NV + chunk * 64) * HV + h;
    float a = 0.f;
#pragma unroll 8
    for (int m = 0; m < 64; m++)
        a = fmaf(cs[m], hp[(size_t)m * HV], a);
    atomicAdd(&g_wit[b * HV + h], a);
}

// ---------------- output projection ----------------
__global__ __launch_bounds__(512)
void proj_kernel(const float* __restrict__ Wp, const float* __restrict__ bp,
                 float* __restrict__ out)
{
    const int b = blockIdx.x;
    const int g = threadIdx.x;
    __shared__ float w[HV];
    w[g] = g_wit[b * HV + g] * (1.0f / NV);
    __syncthreads();
    float accv = bp[g];
    const float* wp = Wp + (size_t)g * HV;
#pragma unroll 8
    for (int h = 0; h < HV; h++)
        accv = fmaf(w[h], wp[h], accv);
    out[b * HV + g] = accv;
}

extern "C" void kernel_launch(void* const* d_in, const int* in_sizes, int n_in,
                              void* d_out, int out_size)
{
    const int*   tokens = (const int*)d_in[0];
    const float* emb    = (const float*)d_in[1];
    const float* W1     = (const float*)d_in[2];
    const float* b1     = (const float*)d_in[3];
    const float* W2     = (const float*)d_in[4];
    const float* b2     = (const float*)d_in[5];
    const float* Wp     = (const float*)d_in[6];
    const float* bp     = (const float*)d_in[7];
    float* out = (float*)d_out;
    (void)in_sizes; (void)n_in; (void)out_size;

    cudaFuncSetAttribute(gemm_t<0>, cudaFuncAttributeMaxDynamicSharedMemorySize, SMEM_SZ);
    cudaFuncSetAttribute(gemm_t<1>, cudaFuncAttributeMaxDynamicSharedMemorySize, SMEM_SZ);
    cudaFuncSetAttribute(gemm_t<2>, cudaFuncAttributeMaxDynamicSharedMemorySize, SMEM_SZ);

    conv_emb_kernel<<<MROWS / 4, 256>>>(tokens, emb);
    conv_w_kernel<0><<<(HV * EV / 4 + 255) / 256, 256>>>(W1);
    conv_w_kernel<1><<<(HV * HV / 4 + 255) / 256, 256>>>(W2);

    gemm_t<0><<<dim3(MROWS / 128, HV / 128), 256, SMEM_SZ>>>(b1);
    gemm_t<1><<<dim3(MROWS / 128, HV / 128), 256, SMEM_SZ>>>(b2);

    norm_kernel<<<MROWS, 128>>>();

    gemm_t<2><<<dim3(136, BV), 256, SMEM_SZ>>>(nullptr);

    witness_kernel<<<dim3(32, BV), 512>>>();
    proj_kernel<<<BV, 512>>>(Wp, bp, out);
}

// round 9
// speedup vs baseline: 3.3355x; 1.0378x over previous
#include <cuda_runtime.h>
#include <cuda_fp16.h>
#include <cstdint>

#define BV 8
#define NV 2048
#define EV 256
#define HV 512
#define MROWS (BV*NV)   // 16384

// ---------------- scratch (static device globals) ----------------
__device__ __half g_A16[(size_t)MROWS * EV];     // fp16 gathered embeddings
__device__ __half g_W1h[HV * EV];
__device__ __half g_W2h[HV * HV];
__device__ __half g_h16[(size_t)MROWS * HV];     // relu(emb@W1+b1), fp16
__device__ float  g_hidden[(size_t)MROWS * HV];  // fp32, for witness
__device__ __half g_n16[(size_t)MROWS * HV];     // normalized rows, fp16
__device__ float g_c[BV * NV];
__device__ float g_wit[BV * HV];

// ---------------- helpers ----------------
__device__ __forceinline__ uint32_t smem_u32(const void* p) {
    uint32_t a;
    asm("{ .reg .u64 t; cvta.to.shared.u64 t, %1; cvt.u32.u64 %0, t; }" : "=r"(a) : "l"(p));
    return a;
}
__device__ __forceinline__ void mma_f16(float* c, const uint32_t* a, const uint32_t* b) {
    asm volatile("mma.sync.aligned.m16n8k16.row.col.f32.f16.f16.f32 "
                 "{%0,%1,%2,%3}, {%4,%5,%6,%7}, {%8,%9}, {%0,%1,%2,%3};"
                 : "+f"(c[0]), "+f"(c[1]), "+f"(c[2]), "+f"(c[3])
                 : "r"(a[0]), "r"(a[1]), "r"(a[2]), "r"(a[3]),
                   "r"(b[0]), "r"(b[1]));
}
#define LDSM4(r0, r1, r2, r3, addr) \
    asm volatile("ldmatrix.sync.aligned.m8n8.x4.shared.b16 {%0,%1,%2,%3}, [%4];" \
                 : "=r"(r0), "=r"(r1), "=r"(r2), "=r"(r3) : "r"(addr))
#define CP_COMMIT asm volatile("cp.async.commit_group;" ::: "memory")
#define CP_WAIT1  asm volatile("cp.async.wait_group 1;" ::: "memory")

// ---------------- fused conversion kernel ----------------
// blocks [0, EMB_BLK): embedding gather -> g_A16
// blocks [EMB_BLK, EMB_BLK+W1_BLK): W1 -> g_W1h
// blocks [EMB_BLK+W1_BLK, ...): W2 -> g_W2h
constexpr int EMB_BLK = MROWS / 4;                 // 4096 (256 thr, 1 float4 each)
constexpr int W1_BLK = (HV * EV / 4) / 256;        // 128
constexpr int W2_BLK = (HV * HV / 4) / 256;        // 256

__global__ __launch_bounds__(256)
void conv_all_kernel(const int* __restrict__ tokens, const float* __restrict__ emb,
                     const float* __restrict__ W1, const float* __restrict__ W2)
{
    const int blk = blockIdx.x;
    if (blk < EMB_BLK) {
        const int idx = blk * 256 + threadIdx.x;
        const int row = idx >> 6;
        const int t = idx & 63;
        const int tok = tokens[row];
        float4 v = *(const float4*)(emb + (size_t)tok * EV + t * 4);
        size_t o = (size_t)row * EV + t * 4;
        *(__half2*)(g_A16 + o)     = __floats2half2_rn(v.x, v.y);
        *(__half2*)(g_A16 + o + 2) = __floats2half2_rn(v.z, v.w);
    } else if (blk < EMB_BLK + W1_BLK) {
        int i = (blk - EMB_BLK) * 256 + threadIdx.x;
        float4 v = ((const float4*)W1)[i];
        size_t o = (size_t)i * 4;
        *(__half2*)(g_W1h + o)     = __floats2half2_rn(v.x, v.y);
        *(__half2*)(g_W1h + o + 2) = __floats2half2_rn(v.z, v.w);
    } else {
        int i = (blk - EMB_BLK - W1_BLK) * 256 + threadIdx.x;
        float4 v = ((const float4*)W2)[i];
        size_t o = (size_t)i * 4;
        *(__half2*)(g_W2h + o)     = __floats2half2_rn(v.x, v.y);
        *(__half2*)(g_W2h + o + 2) = __floats2half2_rn(v.z, v.w);
    }
}

// ============================================================
// Tensor-core GEMM via warp mma.sync, single-pass fp16, fp32 accum.
// MODE 0: relu(A16 @ W1^T + b1) -> g_h16          (K=256)
// MODE 1: h16 @ W2^T + b2       -> g_hidden fp32  (K=512)
// MODE 2: triangular sim tiles  -> softplus -> g_c (K=512)
// Rows of 128B hold k64 fp16. 3-stage cp.async ring (96KB), ONE barrier/stage.
// 256 threads = 8 warps (2M x 4N), warp tile 64x32, block tile 128x128.
// ============================================================
constexpr int STAGE_BYTES = 2 * 16384;       // A tile + B tile
constexpr int NSTAGE = 3;
constexpr int SMEM_SZ = NSTAGE * STAGE_BYTES;   // 96 KB

template<int MODE>
__global__ __launch_bounds__(256, 2)
void gemm_t(const float* __restrict__ bias)
{
    constexpr int KDIM = (MODE == 0) ? EV : HV;
    constexpr int NC = KDIM / 64;
    extern __shared__ __align__(1024) char smem[];
    const uint32_t sbase = smem_u32(smem);
    __shared__ float sBias[128];

    const int tid = threadIdx.x;
    const int lane = tid & 31;
    const int wid = tid >> 5;

    int rowA, rowB, bIdx = 0, ti = 0, tj = 0;
    if (MODE == 2) {
        bIdx = blockIdx.y;
        int rem = blockIdx.x;
        while (rem >= (16 - ti)) { rem -= (16 - ti); ti++; }
        tj = ti + rem;
        rowA = bIdx * NV + ti * 128;
        rowB = bIdx * NV + tj * 128;
    } else {
        rowA = blockIdx.x * 128;
        rowB = blockIdx.y * 128;
    }

    const __half* srcA;
    const __half* srcB;
    if (MODE == 0) {
        srcA = g_A16 + (size_t)rowA * KDIM;
        srcB = g_W1h + (size_t)rowB * KDIM;
    } else if (MODE == 1) {
        srcA = g_h16 + (size_t)rowA * KDIM;
        srcB = g_W2h + (size_t)rowB * KDIM;
    } else {
        srcA = g_n16 + (size_t)rowA * KDIM;
        srcB = g_n16 + (size_t)rowB * KDIM;
    }
    if (MODE < 2 && tid < 128) sBias[tid] = bias[blockIdx.y * 128 + tid];

    // ---- stage loader: 2048 x 16B chunks, 8 per thread ----
    auto load_stage = [&](int stage, int c) {
        const uint32_t stBase = sbase + stage * STAGE_BYTES;
        const int k0 = c * 64;
#pragma unroll
        for (int l = 0; l < 8; l++) {
            int s = l * 256 + tid;
            int comp = s >> 10;          // 0 = A, 1 = B
            int u = s & 1023;
            int r = u >> 3, seg = u & 7;
            const __half* gsrc = (comp ? srcB : srcA) + (size_t)r * KDIM + k0 + seg * 8;
            uint32_t off = (uint32_t)(r * 128 + seg * 16);
            uint32_t dst = stBase + comp * 16384 + (off ^ ((off >> 3) & 0x70));
            asm volatile("cp.async.cg.shared.global [%0], [%1], 16;"
                         :: "r"(dst), "l"(gsrc));
        }
    };

    // ---- per-thread fragment addressing ----
    const int warpM = (wid >> 2) * 64;
    const int warpN = (wid & 3) * 32;
    const uint32_t xorT = (uint32_t)((lane & 7) << 4);
    uint32_t aRow[4], bRow[2];
#pragma unroll
    for (int mi = 0; mi < 4; mi++)
        aRow[mi] = (uint32_t)((warpM + mi * 16 + (lane & 15)) * 128);
    const int bLocal = (lane & 7) + ((lane >> 4) << 3);
#pragma unroll
    for (int p = 0; p < 2; p++)
        bRow[p] = (uint32_t)((warpN + p * 16 + bLocal) * 128);
    const uint32_t aKsel = (uint32_t)((lane >> 4) << 4);
    const uint32_t bKsel = (uint32_t)(((lane >> 3) & 1) << 4);

    float acc[4][4][4];
#pragma unroll
    for (int mi = 0; mi < 4; mi++)
#pragma unroll
        for (int ni = 0; ni < 4; ni++)
#pragma unroll
            for (int k = 0; k < 4; k++) acc[mi][ni][k] = 0.f;

    auto compute_stage = [&](int stage) {
        const uint32_t stBase = sbase + stage * STAGE_BYTES;
        const uint32_t tA = stBase, tB = stBase + 16384;
#pragma unroll
        for (int ks = 0; ks < 4; ks++) {
            const uint32_t kk = (uint32_t)(ks * 32);
            uint32_t bh[4][2];
            {
                uint32_t r0, r1, r2, r3;
                LDSM4(r0, r1, r2, r3, tB + bRow[0] + ((kk + bKsel) ^ xorT));
                bh[0][0] = r0; bh[0][1] = r1; bh[1][0] = r2; bh[1][1] = r3;
                LDSM4(r0, r1, r2, r3, tB + bRow[1] + ((kk + bKsel) ^ xorT));
                bh[2][0] = r0; bh[2][1] = r1; bh[3][0] = r2; bh[3][1] = r3;
            }
            uint32_t a[4][4];
#pragma unroll
            for (int mi = 0; mi < 4; mi++)
                LDSM4(a[mi][0], a[mi][1], a[mi][2], a[mi][3],
                      tA + aRow[mi] + ((kk + aKsel) ^ xorT));
#pragma unroll
            for (int mi = 0; mi < 4; mi++)
#pragma unroll
                for (int ni = 0; ni < 4; ni++)
                    mma_f16(acc[mi][ni], a[mi], bh[ni]);
        }
    };

    // ---- pipelined mainloop: 3-stage ring, ONE barrier per stage ----
    load_stage(0, 0); CP_COMMIT;
    load_stage(1, 1); CP_COMMIT;
    for (int c = 0; c < NC; c++) {
        CP_WAIT1;              // stage c's group done (<=1 pending)
        __syncthreads();       // data visible + all warps done with stage c-1's slot
        if (c + 2 < NC) load_stage((c + 2) % NSTAGE, c + 2);
        CP_COMMIT;             // keep group accounting uniform (empty groups ok)
        compute_stage(c % NSTAGE);
    }

    // ---- epilogue ----
    const int rBase0 = warpM + (lane >> 2);
    const int cBase = warpN + (lane & 3) * 2;

    if (MODE < 2) {
#pragma unroll
        for (int mi = 0; mi < 4; mi++) {
            const int r = rBase0 + mi * 16;
#pragma unroll
            for (int ni = 0; ni < 4; ni++) {
                const int cl = cBase + ni * 8;
                const int gc = blockIdx.y * 128 + cl;
                float v0 = acc[mi][ni][0] + sBias[cl];
                float v1 = acc[mi][ni][1] + sBias[cl + 1];
                float v2 = acc[mi][ni][2] + sBias[cl];
                float v3 = acc[mi][ni][3] + sBias[cl + 1];
                if (MODE == 1) {
                    *(float2*)(g_hidden + (size_t)(rowA + r) * HV + gc) = make_float2(v0, v1);
                    *(float2*)(g_hidden + (size_t)(rowA + r + 8) * HV + gc) = make_float2(v2, v3);
                } else {
                    v0 = fmaxf(v0, 0.f); v1 = fmaxf(v1, 0.f);
                    v2 = fmaxf(v2, 0.f); v3 = fmaxf(v3, 0.f);
                    size_t o0 = (size_t)(rowA + r) * HV + gc;
                    size_t o1 = (size_t)(rowA + r + 8) * HV + gc;
                    *(__half2*)(g_h16 + o0) = __floats2half2_rn(v0, v1);
                    *(__half2*)(g_h16 + o1) = __floats2half2_rn(v2, v3);
                }
            }
        }
    } else {
        // sim epilogue: softplus, dual reduction via smem atomics
        float* rowAcc = (float*)smem;          // [128]
        float* colAcc = (float*)smem + 128;    // [128]
        __syncthreads();                        // all compute done before reusing smem
        if (tid < 256) ((float*)smem)[tid] = 0.f;
        __syncthreads();

        float rowPart[4][2];
        float colPart[4][2];
#pragma unroll
        for (int i = 0; i < 4; i++) {
            rowPart[i][0] = rowPart[i][1] = 0.f;
            colPart[i][0] = colPart[i][1] = 0.f;
        }
#pragma unroll
        for (int mi = 0; mi < 4; mi++)
#pragma unroll
            for (int ni = 0; ni < 4; ni++) {
                float v0 = log1pf(expf(acc[mi][ni][0]));
                float v1 = log1pf(expf(acc[mi][ni][1]));
                float v2 = log1pf(expf(acc[mi][ni][2]));
                float v3 = log1pf(expf(acc[mi][ni][3]));
                rowPart[mi][0] += v0 + v1;
                rowPart[mi][1] += v2 + v3;
                colPart[ni][0] += v0 + v2;
                colPart[ni][1] += v1 + v3;
            }
#pragma unroll
        for (int mi = 0; mi < 4; mi++) {
            atomicAdd(&rowAcc[rBase0 + mi * 16], rowPart[mi][0]);
            atomicAdd(&rowAcc[rBase0 + mi * 16 + 8], rowPart[mi][1]);
        }
#pragma unroll
        for (int ni = 0; ni < 4; ni++) {
            atomicAdd(&colAcc[cBase + ni * 8], colPart[ni][0]);
            atomicAdd(&colAcc[cBase + ni * 8 + 1], colPart[ni][1]);
        }
        __syncthreads();
        if (tid < 128) {
            atomicAdd(&g_c[bIdx * NV + tj * 128 + tid], colAcc[tid]);
            if (ti != tj)
                atomicAdd(&g_c[bIdx * NV + ti * 128 + tid], rowAcc[tid]);
        }
    }
}

// ---------------- normalize -> fp16 (also zeroes g_c / g_wit) ----------------
__global__ __launch_bounds__(128)
void norm_kernel()
{
    const int row = blockIdx.x;
    const int t = threadIdx.x;
    const float4 x = ((const float4*)(g_hidden + (size_t)row * HV))[t];
    float ss = x.x * x.x + x.y * x.y + x.z * x.z + x.w * x.w;
#pragma unroll
    for (int o = 16; o; o >>= 1) ss += __shfl_xor_sync(0xffffffffu, ss, o);
    __shared__ float wsum[4];
    if ((t & 31) == 0) wsum[t >> 5] = ss;
    __syncthreads();
    float tot = wsum[0] + wsum[1] + wsum[2] + wsum[3];
    float inv = 1.0f / fmaxf(sqrtf(tot), 1e-12f);
    size_t o = (size_t)row * HV + t * 4;
    *(__half2*)(g_n16 + o)     = __floats2half2_rn(x.x * inv, x.y * inv);
    *(__half2*)(g_n16 + o + 2) = __floats2half2_rn(x.z * inv, x.w * inv);
    if (t == 0) {
        g_c[row] = 0.f;
        if (row < BV * HV) g_wit[row] = 0.f;
    }
}

// ---------------- witness: partial sums over m-chunks ----------------
__global__ __launch_bounds__(512)
void witness_kernel()
{
    const int chunk = blockIdx.x;   // 32 chunks of 64 rows
    const int b = blockIdx.y;
    const int h = threadIdx.x;
    __shared__ float cs[64];
    if (threadIdx.x < 64) cs[threadIdx.x] = g_c[b * NV + chunk * 64 + threadIdx.x];
    __syncthreads();
    const float* hp = g_hidden + (size_t)(b * NV + chunk * 64) * HV + h;
    float a = 0.f;
#pragma unroll 8
    for (int m = 0; m < 64; m++)
        a = fmaf(cs[m], hp[(size_t)m * HV], a);
    atomicAdd(&g_wit[b * HV + h], a);
}

// ---------------- output projection ----------------
__global__ __launch_bounds__(512)
void proj_kernel(const float* __restrict__ Wp, const float* __restrict__ bp,
                 float* __restrict__ out)
{
    const int b = blockIdx.x;
    const int g = threadIdx.x;
    __shared__ float w[HV];
    w[g] = g_wit[b * HV + g] * (1.0f / NV);
    __syncthreads();
    float accv = bp[g];
    const float* wp = Wp + (size_t)g * HV;
#pragma unroll 8
    for (int h = 0; h < HV; h++)
        accv = fmaf(w[h], wp[h], accv);
    out[b * HV + g] = accv;
}

extern "C" void kernel_launch(void* const* d_in, const int* in_sizes, int n_in,
                              void* d_out, int out_size)
{
    const int*   tokens = (const int*)d_in[0];
    const float* emb    = (const float*)d_in[1];
    const float* W1     = (const float*)d_in[2];
    const float* b1     = (const float*)d_in[3];
    const float* W2     = (const float*)d_in[4];
    const float* b2     = (const float*)d_in[5];
    const float* Wp     = (const float*)d_in[6];
    const float* bp     = (const float*)d_in[7];
    float* out = (float*)d_out;
    (void)in_sizes; (void)n_in; (void)out_size;

    cudaFuncSetAttribute(gemm_t<0>, cudaFuncAttributeMaxDynamicSharedMemorySize, SMEM_SZ);
    cudaFuncSetAttribute(gemm_t<1>, cudaFuncAttributeMaxDynamicSharedMemorySize, SMEM_SZ);
    cudaFuncSetAttribute(gemm_t<2>, cudaFuncAttributeMaxDynamicSharedMemorySize, SMEM_SZ);

    conv_all_kernel<<<EMB_BLK + W1_BLK + W2_BLK, 256>>>(tokens, emb, W1, W2);

    gemm_t<0><<<dim3(MROWS / 128, HV / 128), 256, SMEM_SZ>>>(b1);
    gemm_t<1><<<dim3(MROWS / 128, HV / 128), 256, SMEM_SZ>>>(b2);

    norm_kernel<<<MROWS, 128>>>();

    gemm_t<2><<<dim3(136, BV), 256, SMEM_SZ>>>(nullptr);

    witness_kernel<<<dim3(32, BV), 512>>>();
    proj_kernel<<<BV, 512>>>(Wp, bp, out);
}

// round 10
// speedup vs baseline: 3.5068x; 1.0513x over previous
#include <cuda_runtime.h>
#include <cuda_fp16.h>
#include <cstdint>

#define BV 8
#define NV 2048
#define EV 256
#define HV 512
#define MROWS (BV*NV)   // 16384

// ---------------- scratch (static device globals) ----------------
__device__ __half g_A16[(size_t)MROWS * EV];     // fp16 gathered embeddings
__device__ __half g_W1h[HV * EV];
__device__ __half g_W2h[HV * HV];
__device__ __half g_h16[(size_t)MROWS * HV];     // relu(emb@W1+b1), fp16
__device__ float  g_hidden[(size_t)MROWS * HV];  // fp32, for witness
__device__ __half g_n16[(size_t)MROWS * HV];     // normalized rows, fp16
__device__ float g_c[BV * NV];
__device__ float g_wit[BV * HV];

// ---------------- helpers ----------------
__device__ __forceinline__ uint32_t smem_u32(const void* p) {
    uint32_t a;
    asm("{ .reg .u64 t; cvta.to.shared.u64 t, %1; cvt.u32.u64 %0, t; }" : "=r"(a) : "l"(p));
    return a;
}
__device__ __forceinline__ void mma_f16(float* c, const uint32_t* a, const uint32_t* b) {
    asm volatile("mma.sync.aligned.m16n8k16.row.col.f32.f16.f16.f32 "
                 "{%0,%1,%2,%3}, {%4,%5,%6,%7}, {%8,%9}, {%0,%1,%2,%3};"
                 : "+f"(c[0]), "+f"(c[1]), "+f"(c[2]), "+f"(c[3])
                 : "r"(a[0]), "r"(a[1]), "r"(a[2]), "r"(a[3]),
                   "r"(b[0]), "r"(b[1]));
}
#define LDSM4(r0, r1, r2, r3, addr) \
    asm volatile("ldmatrix.sync.aligned.m8n8.x4.shared.b16 {%0,%1,%2,%3}, [%4];" \
                 : "=r"(r0), "=r"(r1), "=r"(r2), "=r"(r3) : "r"(addr))
#define CP_COMMIT asm volatile("cp.async.commit_group;" ::: "memory")
#define CP_WAIT1  asm volatile("cp.async.wait_group 1;" ::: "memory")

// MUFU-free softplus for |x| <= ~1.1 (sim = dot of unit vectors).
// softplus(x) = x/2 + ln2 + lncosh(x/2); lncosh via even Taylor, err < 2e-7.
__device__ __forceinline__ float softplus_fast(float x) {
    float u = 0.5f * x;
    float v = u * u;
    float p = fmaf(v, 0.002186948854f, -0.006746031746f);
    p = fmaf(v, p, 0.022222222222f);
    p = fmaf(v, p, -0.083333333333f);
    p = fmaf(v, p, 0.5f);
    return fmaf(v, p, u + 0.69314718056f);
}

// ---------------- fused conversion kernel ----------------
constexpr int EMB_BLK = MROWS / 4;                 // 4096
constexpr int W1_BLK = (HV * EV / 4) / 256;        // 128
constexpr int W2_BLK = (HV * HV / 4) / 256;        // 256

__global__ __launch_bounds__(256)
void conv_all_kernel(const int* __restrict__ tokens, const float* __restrict__ emb,
                     const float* __restrict__ W1, const float* __restrict__ W2)
{
    const int blk = blockIdx.x;
    if (blk < EMB_BLK) {
        const int idx = blk * 256 + threadIdx.x;
        const int row = idx >> 6;
        const int t = idx & 63;
        const int tok = tokens[row];
        float4 v = *(const float4*)(emb + (size_t)tok * EV + t * 4);
        size_t o = (size_t)row * EV + t * 4;
        *(__half2*)(g_A16 + o)     = __floats2half2_rn(v.x, v.y);
        *(__half2*)(g_A16 + o + 2) = __floats2half2_rn(v.z, v.w);
    } else if (blk < EMB_BLK + W1_BLK) {
        int i = (blk - EMB_BLK) * 256 + threadIdx.x;
        float4 v = ((const float4*)W1)[i];
        size_t o = (size_t)i * 4;
        *(__half2*)(g_W1h + o)     = __floats2half2_rn(v.x, v.y);
        *(__half2*)(g_W1h + o + 2) = __floats2half2_rn(v.z, v.w);
    } else {
        int i = (blk - EMB_BLK - W1_BLK) * 256 + threadIdx.x;
        float4 v = ((const float4*)W2)[i];
        size_t o = (size_t)i * 4;
        *(__half2*)(g_W2h + o)     = __floats2half2_rn(v.x, v.y);
        *(__half2*)(g_W2h + o + 2) = __floats2half2_rn(v.z, v.w);
    }
}

// ============================================================
// Tensor-core GEMM via warp mma.sync, single-pass fp16, fp32 accum.
// MODE 0: relu(A16 @ W1^T + b1) -> g_h16          (K=256)
// MODE 1: h16 @ W2^T + b2       -> g_hidden fp32  (K=512)
// MODE 2: triangular sim tiles  -> softplus -> g_c (K=512)
// 3-stage cp.async ring (96KB), one barrier per stage.
// 256 threads = 8 warps (2M x 4N), warp tile 64x32, block tile 128x128.
// ============================================================
constexpr int STAGE_BYTES = 2 * 16384;
constexpr int NSTAGE = 3;
constexpr int SMEM_SZ = NSTAGE * STAGE_BYTES;   // 96 KB

template<int MODE>
__global__ __launch_bounds__(256, 2)
void gemm_t(const float* __restrict__ bias)
{
    constexpr int KDIM = (MODE == 0) ? EV : HV;
    constexpr int NC = KDIM / 64;
    extern __shared__ __align__(1024) char smem[];
    const uint32_t sbase = smem_u32(smem);
    __shared__ float sBias[128];

    const int tid = threadIdx.x;
    const int lane = tid & 31;
    const int wid = tid >> 5;

    int rowA, rowB, bIdx = 0, ti = 0, tj = 0;
    if (MODE == 2) {
        bIdx = blockIdx.y;
        int rem = blockIdx.x;
        while (rem >= (16 - ti)) { rem -= (16 - ti); ti++; }
        tj = ti + rem;
        rowA = bIdx * NV + ti * 128;
        rowB = bIdx * NV + tj * 128;
    } else {
        rowA = blockIdx.x * 128;
        rowB = blockIdx.y * 128;
    }

    const __half* srcA;
    const __half* srcB;
    if (MODE == 0) {
        srcA = g_A16 + (size_t)rowA * KDIM;
        srcB = g_W1h + (size_t)rowB * KDIM;
    } else if (MODE == 1) {
        srcA = g_h16 + (size_t)rowA * KDIM;
        srcB = g_W2h + (size_t)rowB * KDIM;
    } else {
        srcA = g_n16 + (size_t)rowA * KDIM;
        srcB = g_n16 + (size_t)rowB * KDIM;
    }
    if (MODE < 2 && tid < 128) sBias[tid] = bias[blockIdx.y * 128 + tid];

    // ---- stage loader: 2048 x 16B chunks, 8 per thread ----
    auto load_stage = [&](int stage, int c) {
        const uint32_t stBase = sbase + stage * STAGE_BYTES;
        const int k0 = c * 64;
#pragma unroll
        for (int l = 0; l < 8; l++) {
            int s = l * 256 + tid;
            int comp = s >> 10;          // 0 = A, 1 = B
            int u = s & 1023;
            int r = u >> 3, seg = u & 7;
            const __half* gsrc = (comp ? srcB : srcA) + (size_t)r * KDIM + k0 + seg * 8;
            uint32_t off = (uint32_t)(r * 128 + seg * 16);
            uint32_t dst = stBase + comp * 16384 + (off ^ ((off >> 3) & 0x70));
            asm volatile("cp.async.cg.shared.global [%0], [%1], 16;"
                         :: "r"(dst), "l"(gsrc));
        }
    };

    // ---- per-thread fragment addressing ----
    const int warpM = (wid >> 2) * 64;
    const int warpN = (wid & 3) * 32;
    const uint32_t xorT = (uint32_t)((lane & 7) << 4);
    uint32_t aRow[4], bRow[2];
#pragma unroll
    for (int mi = 0; mi < 4; mi++)
        aRow[mi] = (uint32_t)((warpM + mi * 16 + (lane & 15)) * 128);
    const int bLocal = (lane & 7) + ((lane >> 4) << 3);
#pragma unroll
    for (int p = 0; p < 2; p++)
        bRow[p] = (uint32_t)((warpN + p * 16 + bLocal) * 128);
    const uint32_t aKsel = (uint32_t)((lane >> 4) << 4);
    const uint32_t bKsel = (uint32_t)(((lane >> 3) & 1) << 4);

    float acc[4][4][4];
#pragma unroll
    for (int mi = 0; mi < 4; mi++)
#pragma unroll
        for (int ni = 0; ni < 4; ni++)
#pragma unroll
            for (int k = 0; k < 4; k++) acc[mi][ni][k] = 0.f;

    auto compute_stage = [&](int stage) {
        const uint32_t stBase = sbase + stage * STAGE_BYTES;
        const uint32_t tA = stBase, tB = stBase + 16384;
#pragma unroll
        for (int ks = 0; ks < 4; ks++) {
            const uint32_t kk = (uint32_t)(ks * 32);
            uint32_t bh[4][2];
            {
                uint32_t r0, r1, r2, r3;
                LDSM4(r0, r1, r2, r3, tB + bRow[0] + ((kk + bKsel) ^ xorT));
                bh[0][0] = r0; bh[0][1] = r1; bh[1][0] = r2; bh[1][1] = r3;
                LDSM4(r0, r1, r2, r3, tB + bRow[1] + ((kk + bKsel) ^ xorT));
                bh[2][0] = r0; bh[2][1] = r1; bh[3][0] = r2; bh[3][1] = r3;
            }
            uint32_t a[4][4];
#pragma unroll
            for (int mi = 0; mi < 4; mi++)
                LDSM4(a[mi][0], a[mi][1], a[mi][2], a[mi][3],
                      tA + aRow[mi] + ((kk + aKsel) ^ xorT));
#pragma unroll
            for (int mi = 0; mi < 4; mi++)
#pragma unroll
                for (int ni = 0; ni < 4; ni++)
                    mma_f16(acc[mi][ni], a[mi], bh[ni]);
        }
    };

    // ---- pipelined mainloop: 3-stage ring, ONE barrier per stage ----
    load_stage(0, 0); CP_COMMIT;
    load_stage(1, 1); CP_COMMIT;
    for (int c = 0; c < NC; c++) {
        CP_WAIT1;
        __syncthreads();
        if (c + 2 < NC) load_stage((c + 2) % NSTAGE, c + 2);
        CP_COMMIT;
        compute_stage(c % NSTAGE);
    }

    // ---- epilogue ----
    const int rBase0 = warpM + (lane >> 2);
    const int cBase = warpN + (lane & 3) * 2;

    if (MODE < 2) {
#pragma unroll
        for (int mi = 0; mi < 4; mi++) {
            const int r = rBase0 + mi * 16;
#pragma unroll
            for (int ni = 0; ni < 4; ni++) {
                const int cl = cBase + ni * 8;
                const int gc = blockIdx.y * 128 + cl;
                float v0 = acc[mi][ni][0] + sBias[cl];
                float v1 = acc[mi][ni][1] + sBias[cl + 1];
                float v2 = acc[mi][ni][2] + sBias[cl];
                float v3 = acc[mi][ni][3] + sBias[cl + 1];
                if (MODE == 1) {
                    *(float2*)(g_hidden + (size_t)(rowA + r) * HV + gc) = make_float2(v0, v1);
                    *(float2*)(g_hidden + (size_t)(rowA + r + 8) * HV + gc) = make_float2(v2, v3);
                } else {
                    v0 = fmaxf(v0, 0.f); v1 = fmaxf(v1, 0.f);
                    v2 = fmaxf(v2, 0.f); v3 = fmaxf(v3, 0.f);
                    size_t o0 = (size_t)(rowA + r) * HV + gc;
                    size_t o1 = (size_t)(rowA + r + 8) * HV + gc;
                    *(__half2*)(g_h16 + o0) = __floats2half2_rn(v0, v1);
                    *(__half2*)(g_h16 + o1) = __floats2half2_rn(v2, v3);
                }
            }
        }
    } else {
        // sim epilogue: MUFU-free softplus, dual reduction via smem atomics
        float* rowAcc = (float*)smem;          // [128]
        float* colAcc = (float*)smem + 128;    // [128]
        __syncthreads();                        // mainloop done before smem reuse
        if (tid < 256) ((float*)smem)[tid] = 0.f;
        __syncthreads();

        float rowPart[4][2];
        float colPart[4][2];
#pragma unroll
        for (int i = 0; i < 4; i++) {
            rowPart[i][0] = rowPart[i][1] = 0.f;
            colPart[i][0] = colPart[i][1] = 0.f;
        }
#pragma unroll
        for (int mi = 0; mi < 4; mi++)
#pragma unroll
            for (int ni = 0; ni < 4; ni++) {
                float v0 = softplus_fast(acc[mi][ni][0]);
                float v1 = softplus_fast(acc[mi][ni][1]);
                float v2 = softplus_fast(acc[mi][ni][2]);
                float v3 = softplus_fast(acc[mi][ni][3]);
                rowPart[mi][0] += v0 + v1;
                rowPart[mi][1] += v2 + v3;
                colPart[ni][0] += v0 + v2;
                colPart[ni][1] += v1 + v3;
            }
#pragma unroll
        for (int mi = 0; mi < 4; mi++) {
            atomicAdd(&rowAcc[rBase0 + mi * 16], rowPart[mi][0]);
            atomicAdd(&rowAcc[rBase0 + mi * 16 + 8], rowPart[mi][1]);
        }
#pragma unroll
        for (int ni = 0; ni < 4; ni++) {
            atomicAdd(&colAcc[cBase + ni * 8], colPart[ni][0]);
            atomicAdd(&colAcc[cBase + ni * 8 + 1], colPart[ni][1]);
        }
        __syncthreads();
        if (tid < 128) {
            atomicAdd(&g_c[bIdx * NV + tj * 128 + tid], colAcc[tid]);
            if (ti != tj)
                atomicAdd(&g_c[bIdx * NV + ti * 128 + tid], rowAcc[tid]);
        }
    }
}

// ---------------- normalize -> fp16 (also zeroes g_c / g_wit) ----------------
__global__ __launch_bounds__(128)
void norm_kernel()
{
    const int row = blockIdx.x;
    const int t = threadIdx.x;
    const float4 x = ((const float4*)(g_hidden + (size_t)row * HV))[t];
    float ss = x.x * x.x + x.y * x.y + x.z * x.z + x.w * x.w;
#pragma unroll
    for (int o = 16; o; o >>= 1) ss += __shfl_xor_sync(0xffffffffu, ss, o);
    __shared__ float wsum[4];
    if ((t & 31) == 0) wsum[t >> 5] = ss;
    __syncthreads();
    float tot = wsum[0] + wsum[1] + wsum[2] + wsum[3];
    float inv = 1.0f / fmaxf(sqrtf(tot), 1e-12f);
    size_t o = (size_t)row * HV + t * 4;
    *(__half2*)(g_n16 + o)     = __floats2half2_rn(x.x * inv, x.y * inv);
    *(__half2*)(g_n16 + o + 2) = __floats2half2_rn(x.z * inv, x.w * inv);
    if (t == 0) {
        g_c[row] = 0.f;
        if (row < BV * HV) g_wit[row] = 0.f;
    }
}

// ---------------- witness: partial sums over m-chunks ----------------
__global__ __launch_bounds__(512)
void witness_kernel()
{
    const int chunk = blockIdx.x;   // 32 chunks of 64 rows
    const int b = blockIdx.y;
    const int h = threadIdx.x;
    __shared__ float cs[64];
    if (threadIdx.x < 64) cs[threadIdx.x] = g_c[b * NV + chunk * 64 + threadIdx.x];
    __syncthreads();
    const float* hp = g_hidden + (size_t)(b * NV + chunk * 64) * HV + h;
    float a = 0.f;
#pragma unroll 8
    for (int m = 0; m < 64; m++)
        a = fmaf(cs[m], hp[(size_t)m * HV], a);
    atomicAdd(&g_wit[b * HV + h], a);
}

// ---------------- output projection ----------------
__global__ __launch_bounds__(512)
void proj_kernel(const float* __restrict__ Wp, const float* __restrict__ bp,
                 float* __restrict__ out)
{
    const int b = blockIdx.x;
    const int g = threadIdx.x;
    __shared__ float w[HV];
    w[g] = g_wit[b * HV + g] * (1.0f / NV);
    __syncthreads();
    float accv = bp[g];
    const float* wp = Wp + (size_t)g * HV;
#pragma unroll 8
    for (int h = 0; h < HV; h++)
        accv = fmaf(w[h], wp[h], accv);
    out[b * HV + g] = accv;
}

extern "C" void kernel_launch(void* const* d_in, const int* in_sizes, int n_in,
                              void* d_out, int out_size)
{
    const int*   tokens = (const int*)d_in[0];
    const float* emb    = (const float*)d_in[1];
    const float* W1     = (const float*)d_in[2];
    const float* b1     = (const float*)d_in[3];
    const float* W2     = (const float*)d_in[4];
    const float* b2     = (const float*)d_in[5];
    const float* Wp     = (const float*)d_in[6];
    const float* bp     = (const float*)d_in[7];
    float* out = (float*)d_out;
    (void)in_sizes; (void)n_in; (void)out_size;

    cudaFuncSetAttribute(gemm_t<0>, cudaFuncAttributeMaxDynamicSharedMemorySize, SMEM_SZ);
    cudaFuncSetAttribute(gemm_t<1>, cudaFuncAttributeMaxDynamicSharedMemorySize, SMEM_SZ);
    cudaFuncSetAttribute(gemm_t<2>, cudaFuncAttributeMaxDynamicSharedMemorySize, SMEM_SZ);

    conv_all_kernel<<<EMB_BLK + W1_BLK + W2_BLK, 256>>>(tokens, emb, W1, W2);

    gemm_t<0><<<dim3(MROWS / 128, HV / 128), 256, SMEM_SZ>>>(b1);
    gemm_t<1><<<dim3(MROWS / 128, HV / 128), 256, SMEM_SZ>>>(b2);

    norm_kernel<<<MROWS, 128>>>();

    gemm_t<2><<<dim3(136, BV), 256, SMEM_SZ>>>(nullptr);

    witness_kernel<<<dim3(32, BV), 512>>>();
    proj_kernel<<<BV, 512>>>(Wp, bp, out);
}